// round 3
// baseline (speedup 1.0000x reference)
#include <cuda_runtime.h>
#include <cuda_bf16.h>
#include <math.h>

// Problem constants
#define BB 4
#define SS 2048
#define DD 1024
#define HH 16
#define HD 64
#define FF 4096
#define ROWS (BB*SS)          // 8192

// ---------------- scratch (static device globals; no allocs allowed) ----------
__device__ float g_xn [ROWS*DD];   // LN output (reused for LN1 and LN2)
__device__ float g_q  [ROWS*DD];
__device__ float g_k  [ROWS*DD];
__device__ float g_v  [ROWS*DD];
__device__ float g_att[ROWS*DD];   // attention output [B,S,D]
__device__ float g_x1 [ROWS*DD];   // after first residual
__device__ float g_h  [ROWS*FF];   // FFN hidden

// ---------------- helpers -----------------------------------------------------
__device__ __forceinline__ unsigned f2tf32(float f) {
    unsigned r;
    asm("cvt.rna.tf32.f32 %0, %1;" : "=r"(r) : "f"(f));
    return r;
}

// mma.m16n8k8 tf32 frag conventions (gid=lane>>2, tig=lane&3):
//   A (m16 k8, row): a0=A[gid][tig] a1=A[gid+8][tig] a2=A[gid][tig+4] a3=A[gid+8][tig+4]
//   B (k8 n8, col):  b0=B[tig][gid] b1=B[tig+4][gid]
//   C (m16 n8):      c0=C[gid][2tig] c1=C[gid][2tig+1] c2=C[gid+8][2tig] c3=C[gid+8][2tig+1]
__device__ __forceinline__ void mma_tf32(float* d, const unsigned* a, unsigned b0, unsigned b1) {
    asm volatile(
        "mma.sync.aligned.m16n8k8.row.col.f32.tf32.tf32.f32 "
        "{%0,%1,%2,%3}, {%4,%5,%6,%7}, {%8,%9}, {%0,%1,%2,%3};"
        : "+f"(d[0]), "+f"(d[1]), "+f"(d[2]), "+f"(d[3])
        : "r"(a[0]), "r"(a[1]), "r"(a[2]), "r"(a[3]), "r"(b0), "r"(b1));
}

// ---------------- LayerNorm: one block per row, 256 threads -------------------
__global__ __launch_bounds__(256)
void ln_kernel(const float* __restrict__ X, const float* __restrict__ g,
               const float* __restrict__ be, float* __restrict__ Y)
{
    int row = blockIdx.x;
    int tid = threadIdx.x;
    const float4 v = ((const float4*)(X + (long)row * DD))[tid];

    float s = v.x + v.y + v.z + v.w;
    float q = v.x*v.x + v.y*v.y + v.z*v.z + v.w*v.w;
    #pragma unroll
    for (int o = 16; o > 0; o >>= 1) {
        s += __shfl_xor_sync(0xffffffffu, s, o);
        q += __shfl_xor_sync(0xffffffffu, q, o);
    }
    __shared__ float ss[8], sq[8];
    int wid = tid >> 5, lane = tid & 31;
    if (lane == 0) { ss[wid] = s; sq[wid] = q; }
    __syncthreads();
    if (tid < 32) {
        float s2 = (tid < 8) ? ss[tid] : 0.f;
        float q2 = (tid < 8) ? sq[tid] : 0.f;
        #pragma unroll
        for (int o = 4; o > 0; o >>= 1) {
            s2 += __shfl_xor_sync(0xffffffffu, s2, o);
            q2 += __shfl_xor_sync(0xffffffffu, q2, o);
        }
        if (tid == 0) { ss[0] = s2; sq[0] = q2; }
    }
    __syncthreads();
    const float mean = ss[0] * (1.f / DD);
    const float var  = sq[0] * (1.f / DD) - mean * mean;
    const float rstd = rsqrtf(var + 1e-5f);

    const float4 gg = ((const float4*)g )[tid];
    const float4 bb = ((const float4*)be)[tid];
    float4 o4;
    o4.x = (v.x - mean) * rstd * gg.x + bb.x;
    o4.y = (v.y - mean) * rstd * gg.y + bb.y;
    o4.z = (v.z - mean) * rstd * gg.z + bb.z;
    o4.w = (v.w - mean) * rstd * gg.w + bb.w;
    ((float4*)(Y + (long)row * DD))[tid] = o4;
}

// ---------------- tf32 tensor-core GEMM: C = A(MxK) @ B(KxN) + bias ----------
// 128 threads (4 warps), block tile 128x128, BK=16, warp tile 64x64.
// EPI: 0 = none, 1 = exact GELU, 2 = add residual R
template<int EPI>
__global__ __launch_bounds__(128)
void gemm_tf32(const float* __restrict__ A, const float* __restrict__ B,
               const float* __restrict__ bias, const float* __restrict__ R,
               float* __restrict__ C, int M, int N, int K)
{
    __shared__ unsigned As[128][20];   // [m][k], pad 20 -> conflict-free frag loads
    __shared__ unsigned Bs[16][136];   // [k][n], pad 136 (=8 mod 32) -> conflict-free

    const int tid  = threadIdx.x;
    const int wid  = tid >> 5;
    const int lane = tid & 31;
    const int gid  = lane >> 2;   // 0..7
    const int tig  = lane & 3;    // 0..3
    const int warpM = (wid >> 1) * 64;
    const int warpN = (wid & 1) * 64;
    const int bm = blockIdx.y * 128;
    const int bn = blockIdx.x * 128;

    float acc[4][8][4];
    #pragma unroll
    for (int mt = 0; mt < 4; mt++)
        #pragma unroll
        for (int nt = 0; nt < 8; nt++)
            #pragma unroll
            for (int r = 0; r < 4; r++) acc[mt][nt][r] = 0.f;

    int arow[4], ac4[4], brow[4], bc4[4];
    #pragma unroll
    for (int l = 0; l < 4; l++) {
        int f = tid + l * 128;
        arow[l] = f >> 2;  ac4[l] = (f & 3) * 4;    // A: 128 rows x 4 float4
        brow[l] = f >> 5;  bc4[l] = (f & 31) * 4;   // B: 16 rows x 32 float4
    }
    const float* Ablk = A + (long)bm * K;
    const float* Bblk = B + bn;

    float4 aS[4], bS[4];
    #pragma unroll
    for (int l = 0; l < 4; l++) {
        aS[l] = *(const float4*)&Ablk[(long)arow[l] * K + ac4[l]];
        bS[l] = *(const float4*)&Bblk[(long)brow[l] * N + bc4[l]];
    }
    #pragma unroll
    for (int l = 0; l < 4; l++) {
        *(uint4*)&As[arow[l]][ac4[l]] =
            make_uint4(f2tf32(aS[l].x), f2tf32(aS[l].y), f2tf32(aS[l].z), f2tf32(aS[l].w));
        *(uint4*)&Bs[brow[l]][bc4[l]] =
            make_uint4(f2tf32(bS[l].x), f2tf32(bS[l].y), f2tf32(bS[l].z), f2tf32(bS[l].w));
    }
    __syncthreads();

    for (int k0 = 16; k0 <= K; k0 += 16) {
        const bool more = (k0 < K);
        if (more) {
            #pragma unroll
            for (int l = 0; l < 4; l++) {
                aS[l] = *(const float4*)&Ablk[(long)arow[l] * K + k0 + ac4[l]];
                bS[l] = *(const float4*)&Bblk[(long)(k0 + brow[l]) * N + bc4[l]];
            }
        }
        #pragma unroll
        for (int ks = 0; ks < 16; ks += 8) {
            unsigned af[4][4];
            #pragma unroll
            for (int mt = 0; mt < 4; mt++) {
                int r0 = warpM + mt * 16 + gid;
                af[mt][0] = As[r0    ][ks + tig];
                af[mt][1] = As[r0 + 8][ks + tig];
                af[mt][2] = As[r0    ][ks + tig + 4];
                af[mt][3] = As[r0 + 8][ks + tig + 4];
            }
            #pragma unroll
            for (int nt = 0; nt < 8; nt++) {
                int cc = warpN + nt * 8 + gid;
                unsigned b0 = Bs[ks + tig    ][cc];
                unsigned b1 = Bs[ks + tig + 4][cc];
                #pragma unroll
                for (int mt = 0; mt < 4; mt++)
                    mma_tf32(acc[mt][nt], af[mt], b0, b1);
            }
        }
        __syncthreads();
        if (more) {
            #pragma unroll
            for (int l = 0; l < 4; l++) {
                *(uint4*)&As[arow[l]][ac4[l]] =
                    make_uint4(f2tf32(aS[l].x), f2tf32(aS[l].y), f2tf32(aS[l].z), f2tf32(aS[l].w));
                *(uint4*)&Bs[brow[l]][bc4[l]] =
                    make_uint4(f2tf32(bS[l].x), f2tf32(bS[l].y), f2tf32(bS[l].z), f2tf32(bS[l].w));
            }
            __syncthreads();
        }
    }

    #pragma unroll
    for (int mt = 0; mt < 4; mt++) {
        int r0 = bm + warpM + mt * 16 + gid;
        #pragma unroll
        for (int nt = 0; nt < 8; nt++) {
            int c0 = bn + warpN + nt * 8 + tig * 2;
            float bv0 = bias[c0], bv1 = bias[c0 + 1];
            float v00 = acc[mt][nt][0] + bv0;
            float v01 = acc[mt][nt][1] + bv1;
            float v10 = acc[mt][nt][2] + bv0;
            float v11 = acc[mt][nt][3] + bv1;
            if (EPI == 1) {
                v00 = 0.5f * v00 * (1.f + erff(v00 * 0.70710678118654752f));
                v01 = 0.5f * v01 * (1.f + erff(v01 * 0.70710678118654752f));
                v10 = 0.5f * v10 * (1.f + erff(v10 * 0.70710678118654752f));
                v11 = 0.5f * v11 * (1.f + erff(v11 * 0.70710678118654752f));
            } else if (EPI == 2) {
                v00 += R[(long)r0 * N + c0];
                v01 += R[(long)r0 * N + c0 + 1];
                v10 += R[(long)(r0 + 8) * N + c0];
                v11 += R[(long)(r0 + 8) * N + c0 + 1];
            }
            *(float2*)&C[(long)r0 * N + c0]       = make_float2(v00, v01);
            *(float2*)&C[(long)(r0 + 8) * N + c0] = make_float2(v10, v11);
        }
    }
}

// ---------------- Flash attention, tf32 tensor cores -------------------------
// BQ=64, BKV=64, HD=64. 128 threads (4 warps); warp w owns q-rows [w*16, w*16+16).
// Smem tiles padded to 72 cols: frag-load bank patterns 8*gid+tig / 8*tig+gid
// are conflict-free. grid: (S/64, B*H).
__global__ __launch_bounds__(128)
void attn_tc(const float* __restrict__ Q, const float* __restrict__ Km,
             const float* __restrict__ V, float* __restrict__ O)
{
    constexpr int PAD = 72;
    extern __shared__ unsigned smem[];
    unsigned* Qs = smem;               // [qrow][d]   64x72 tf32
    unsigned* Ks = Qs + 64 * PAD;      // [kvrow][d]  64x72 tf32
    unsigned* Vs = Ks + 64 * PAD;      // [kvrow][d]  64x72 tf32
    unsigned* Ps = Vs + 64 * PAD;      // [qrow][kv]  64x72 tf32

    const int tid  = threadIdx.x;
    const int wid  = tid >> 5;
    const int lane = tid & 31;
    const int gid  = lane >> 2;
    const int tig  = lane & 3;
    const int w16  = wid * 16;
    const int q0   = blockIdx.x * 64;
    const int b    = blockIdx.y / HH;
    const int h    = blockIdx.y % HH;
    const long headoff = (long)h * HD;
    const long rowbase = (long)b * SS;

    // load Q tile -> tf32 smem [row][d]
    #pragma unroll
    for (int l = 0; l < 8; l++) {
        int f   = tid + l * 128;       // 0..1023 float4s
        int row = f >> 4;
        int c4  = (f & 15) * 4;
        float4 a = *(const float4*)&Q[(rowbase + q0 + row) * DD + headoff + c4];
        *(uint4*)&Qs[row * PAD + c4] =
            make_uint4(f2tf32(a.x), f2tf32(a.y), f2tf32(a.z), f2tf32(a.w));
    }

    float m0 = -INFINITY, m1 = -INFINITY, l0 = 0.f, l1 = 0.f;
    float o[8][4];
    #pragma unroll
    for (int nt = 0; nt < 8; nt++)
        #pragma unroll
        for (int r = 0; r < 4; r++) o[nt][r] = 0.f;

    for (int t = 0; t < SS / 64; t++) {
        __syncthreads();               // all warps done with prev K/V tiles
        const int k0 = t * 64;
        #pragma unroll
        for (int l = 0; l < 8; l++) {
            int f   = tid + l * 128;
            int row = f >> 4;
            int c4  = (f & 15) * 4;
            float4 a = *(const float4*)&Km[(rowbase + k0 + row) * DD + headoff + c4];
            *(uint4*)&Ks[row * PAD + c4] =
                make_uint4(f2tf32(a.x), f2tf32(a.y), f2tf32(a.z), f2tf32(a.w));
            float4 vv = *(const float4*)&V[(rowbase + k0 + row) * DD + headoff + c4];
            *(uint4*)&Vs[row * PAD + c4] =
                make_uint4(f2tf32(vv.x), f2tf32(vv.y), f2tf32(vv.z), f2tf32(vv.w));
        }
        __syncthreads();

        // S = Q @ K^T : warp computes m16 x n64, k=64
        float sacc[8][4];
        #pragma unroll
        for (int nt = 0; nt < 8; nt++)
            #pragma unroll
            for (int r = 0; r < 4; r++) sacc[nt][r] = 0.f;
        #pragma unroll
        for (int kt = 0; kt < 8; kt++) {
            unsigned a[4];
            a[0] = Qs[(w16 + gid    ) * PAD + kt * 8 + tig];
            a[1] = Qs[(w16 + gid + 8) * PAD + kt * 8 + tig];
            a[2] = Qs[(w16 + gid    ) * PAD + kt * 8 + tig + 4];
            a[3] = Qs[(w16 + gid + 8) * PAD + kt * 8 + tig + 4];
            #pragma unroll
            for (int nt = 0; nt < 8; nt++) {
                unsigned b0 = Ks[(nt * 8 + gid) * PAD + kt * 8 + tig];
                unsigned b1 = Ks[(nt * 8 + gid) * PAD + kt * 8 + tig + 4];
                mma_tf32(sacc[nt], a, b0, b1);
            }
        }

        // online softmax: thread holds rows (w16+gid) [c0,c1] and (w16+gid+8) [c2,c3]
        float p[8][4];
        float rm0 = -INFINITY, rm1 = -INFINITY;
        #pragma unroll
        for (int nt = 0; nt < 8; nt++) {
            #pragma unroll
            for (int r = 0; r < 4; r++) p[nt][r] = sacc[nt][r] * 0.125f;  // 1/sqrt(64)
            rm0 = fmaxf(rm0, fmaxf(p[nt][0], p[nt][1]));
            rm1 = fmaxf(rm1, fmaxf(p[nt][2], p[nt][3]));
        }
        #pragma unroll
        for (int off = 1; off < 4; off <<= 1) {
            rm0 = fmaxf(rm0, __shfl_xor_sync(0xffffffffu, rm0, off));
            rm1 = fmaxf(rm1, __shfl_xor_sync(0xffffffffu, rm1, off));
        }
        float mn0 = fmaxf(m0, rm0), mn1 = fmaxf(m1, rm1);
        float corr0 = __expf(m0 - mn0), corr1 = __expf(m1 - mn1);
        m0 = mn0; m1 = mn1;
        float rs0 = 0.f, rs1 = 0.f;
        #pragma unroll
        for (int nt = 0; nt < 8; nt++) {
            p[nt][0] = __expf(p[nt][0] - mn0);
            p[nt][1] = __expf(p[nt][1] - mn0);
            p[nt][2] = __expf(p[nt][2] - mn1);
            p[nt][3] = __expf(p[nt][3] - mn1);
            rs0 += p[nt][0] + p[nt][1];
            rs1 += p[nt][2] + p[nt][3];
        }
        #pragma unroll
        for (int off = 1; off < 4; off <<= 1) {
            rs0 += __shfl_xor_sync(0xffffffffu, rs0, off);
            rs1 += __shfl_xor_sync(0xffffffffu, rs1, off);
        }
        l0 = l0 * corr0 + rs0;
        l1 = l1 * corr1 + rs1;
        #pragma unroll
        for (int nt = 0; nt < 8; nt++) {
            o[nt][0] *= corr0; o[nt][1] *= corr0;
            o[nt][2] *= corr1; o[nt][3] *= corr1;
        }

        // P -> smem (tf32); warp reads back only its OWN rows -> __syncwarp suffices
        #pragma unroll
        for (int nt = 0; nt < 8; nt++) {
            *(uint2*)&Ps[(w16 + gid    ) * PAD + nt * 8 + tig * 2] =
                make_uint2(f2tf32(p[nt][0]), f2tf32(p[nt][1]));
            *(uint2*)&Ps[(w16 + gid + 8) * PAD + nt * 8 + tig * 2] =
                make_uint2(f2tf32(p[nt][2]), f2tf32(p[nt][3]));
        }
        __syncwarp();

        // O += P @ V : A = P[m=q][k=kv], B = V[k=kv][n=d] (col-major = natural)
        #pragma unroll
        for (int kt = 0; kt < 8; kt++) {
            unsigned a[4];
            a[0] = Ps[(w16 + gid    ) * PAD + kt * 8 + tig];
            a[1] = Ps[(w16 + gid + 8) * PAD + kt * 8 + tig];
            a[2] = Ps[(w16 + gid    ) * PAD + kt * 8 + tig + 4];
            a[3] = Ps[(w16 + gid + 8) * PAD + kt * 8 + tig + 4];
            #pragma unroll
            for (int nt = 0; nt < 8; nt++) {
                unsigned b0 = Vs[(kt * 8 + tig    ) * PAD + nt * 8 + gid];
                unsigned b1 = Vs[(kt * 8 + tig + 4) * PAD + nt * 8 + gid];
                mma_tf32(o[nt], a, b0, b1);
            }
        }
        __syncwarp();   // P reads done before next iter's writes
    }

    // write O rows (w16+gid) and (w16+gid+8)
    const float inv0 = 1.f / l0, inv1 = 1.f / l1;
    const long r0 = rowbase + q0 + w16 + gid;
    #pragma unroll
    for (int nt = 0; nt < 8; nt++) {
        int c = nt * 8 + tig * 2;
        *(float2*)&O[r0 * DD + headoff + c] =
            make_float2(o[nt][0] * inv0, o[nt][1] * inv0);
        *(float2*)&O[(r0 + 8) * DD + headoff + c] =
            make_float2(o[nt][2] * inv1, o[nt][3] * inv1);
    }
}

// ---------------- launch -----------------------------------------------------
extern "C" void kernel_launch(void* const* d_in, const int* in_sizes, int n_in,
                              void* d_out, int out_size)
{
    const float* x   = (const float*)d_in[0];
    const float* Wq  = (const float*)d_in[1];
    const float* bq  = (const float*)d_in[2];
    const float* Wk  = (const float*)d_in[3];
    const float* bk  = (const float*)d_in[4];
    const float* Wv  = (const float*)d_in[5];
    const float* bv  = (const float*)d_in[6];
    const float* Wo  = (const float*)d_in[7];
    const float* bo  = (const float*)d_in[8];
    const float* W1  = (const float*)d_in[9];
    const float* b1  = (const float*)d_in[10];
    const float* W2  = (const float*)d_in[11];
    const float* b2  = (const float*)d_in[12];
    const float* g1  = (const float*)d_in[13];
    const float* be1 = (const float*)d_in[14];
    const float* g2  = (const float*)d_in[15];
    const float* be2 = (const float*)d_in[16];
    float* out = (float*)d_out;

    float *p_xn, *p_q, *p_k, *p_v, *p_att, *p_x1, *p_h;
    cudaGetSymbolAddress((void**)&p_xn,  g_xn);
    cudaGetSymbolAddress((void**)&p_q,   g_q);
    cudaGetSymbolAddress((void**)&p_k,   g_k);
    cudaGetSymbolAddress((void**)&p_v,   g_v);
    cudaGetSymbolAddress((void**)&p_att, g_att);
    cudaGetSymbolAddress((void**)&p_x1,  g_x1);
    cudaGetSymbolAddress((void**)&p_h,   g_h);

    const int attn_smem = 4 * 64 * 72 * (int)sizeof(unsigned);   // 73728 B
    cudaFuncSetAttribute(attn_tc, cudaFuncAttributeMaxDynamicSharedMemorySize, attn_smem);

    dim3 gemmDD(DD / 128, ROWS / 128);   // (8, 64)
    dim3 gemmDF(FF / 128, ROWS / 128);   // (32, 64)

    // 1. LN1
    ln_kernel<<<ROWS, 256>>>(x, g1, be1, p_xn);
    // 2-4. QKV projections (tf32 tensor cores)
    gemm_tf32<0><<<gemmDD, 128>>>(p_xn, Wq, bq, nullptr, p_q, ROWS, DD, DD);
    gemm_tf32<0><<<gemmDD, 128>>>(p_xn, Wk, bk, nullptr, p_k, ROWS, DD, DD);
    gemm_tf32<0><<<gemmDD, 128>>>(p_xn, Wv, bv, nullptr, p_v, ROWS, DD, DD);
    // 5. attention (tf32 tensor-core flash)
    dim3 attnGrid(SS / 64, BB * HH);     // (32, 64)
    attn_tc<<<attnGrid, 128, attn_smem>>>(p_q, p_k, p_v, p_att);
    // 6. output projection + residual
    gemm_tf32<2><<<gemmDD, 128>>>(p_att, Wo, bo, x, p_x1, ROWS, DD, DD);
    // 7. LN2
    ln_kernel<<<ROWS, 256>>>(p_x1, g2, be2, p_xn);
    // 8. FFN up + GELU
    gemm_tf32<1><<<gemmDF, 128>>>(p_xn, W1, b1, nullptr, p_h, ROWS, FF, DD);
    // 9. FFN down + residual -> out
    gemm_tf32<2><<<gemmDD, 128>>>(p_h, W2, b2, p_x1, out, ROWS, DD, FF);
}

// round 5
// speedup vs baseline: 1.0168x; 1.0168x over previous
#include <cuda_runtime.h>
#include <cuda_bf16.h>
#include <math.h>

// Problem constants
#define BB 4
#define SS 2048
#define DD 1024
#define HH 16
#define HD 64
#define FF 4096
#define ROWS (BB*SS)          // 8192

// ---------------- scratch (static device globals; no allocs allowed) ----------
__device__ float g_xn [ROWS*DD];   // LN output (reused for LN1 and LN2)
__device__ float g_q  [ROWS*DD];
__device__ float g_k  [ROWS*DD];
__device__ float g_v  [ROWS*DD];
__device__ float g_att[ROWS*DD];   // attention output [B,S,D]
__device__ float g_x1 [ROWS*DD];   // after first residual
__device__ float g_h  [ROWS*FF];   // FFN hidden

// ---------------- helpers -----------------------------------------------------
__device__ __forceinline__ unsigned f2tf32(float f) {
    unsigned r;
    asm("cvt.rna.tf32.f32 %0, %1;" : "=r"(r) : "f"(f));
    return r;
}

// mma.m16n8k8 tf32 frag conventions (gid=lane>>2, tig=lane&3):
//   A (m16 k8, row): a0=A[gid][tig] a1=A[gid+8][tig] a2=A[gid][tig+4] a3=A[gid+8][tig+4]
//   B (k8 n8, col):  b0=B[tig][gid] b1=B[tig+4][gid]
//   C (m16 n8):      c0=C[gid][2tig] c1=C[gid][2tig+1] c2=C[gid+8][2tig] c3=C[gid+8][2tig+1]
__device__ __forceinline__ void mma_tf32(float* d, const unsigned* a, unsigned b0, unsigned b1) {
    asm volatile(
        "mma.sync.aligned.m16n8k8.row.col.f32.tf32.tf32.f32 "
        "{%0,%1,%2,%3}, {%4,%5,%6,%7}, {%8,%9}, {%0,%1,%2,%3};"
        : "+f"(d[0]), "+f"(d[1]), "+f"(d[2]), "+f"(d[3])
        : "r"(a[0]), "r"(a[1]), "r"(a[2]), "r"(a[3]), "r"(b0), "r"(b1));
}

// ---------------- LayerNorm: one block per row, 256 threads -------------------
__global__ __launch_bounds__(256)
void ln_kernel(const float* __restrict__ X, const float* __restrict__ g,
               const float* __restrict__ be, float* __restrict__ Y)
{
    int row = blockIdx.x;
    int tid = threadIdx.x;
    const float4 v = ((const float4*)(X + (long)row * DD))[tid];

    float s = v.x + v.y + v.z + v.w;
    float q = v.x*v.x + v.y*v.y + v.z*v.z + v.w*v.w;
    #pragma unroll
    for (int o = 16; o > 0; o >>= 1) {
        s += __shfl_xor_sync(0xffffffffu, s, o);
        q += __shfl_xor_sync(0xffffffffu, q, o);
    }
    __shared__ float ss[8], sq[8];
    int wid = tid >> 5, lane = tid & 31;
    if (lane == 0) { ss[wid] = s; sq[wid] = q; }
    __syncthreads();
    if (tid < 32) {
        float s2 = (tid < 8) ? ss[tid] : 0.f;
        float q2 = (tid < 8) ? sq[tid] : 0.f;
        #pragma unroll
        for (int o = 4; o > 0; o >>= 1) {
            s2 += __shfl_xor_sync(0xffffffffu, s2, o);
            q2 += __shfl_xor_sync(0xffffffffu, q2, o);
        }
        if (tid == 0) { ss[0] = s2; sq[0] = q2; }
    }
    __syncthreads();
    const float mean = ss[0] * (1.f / DD);
    const float var  = sq[0] * (1.f / DD) - mean * mean;
    const float rstd = rsqrtf(var + 1e-5f);

    const float4 gg = ((const float4*)g )[tid];
    const float4 bb = ((const float4*)be)[tid];
    float4 o4;
    o4.x = (v.x - mean) * rstd * gg.x + bb.x;
    o4.y = (v.y - mean) * rstd * gg.y + bb.y;
    o4.z = (v.z - mean) * rstd * gg.z + bb.z;
    o4.w = (v.w - mean) * rstd * gg.w + bb.w;
    ((float4*)(Y + (long)row * DD))[tid] = o4;
}

// ---------------- tf32 tensor-core GEMM body ---------------------------------
// 256 threads (8 warps), block tile 128x128, BK=16, double-buffered smem.
// Warp grid 2(m) x 4(n): warp tile 64x32 -> acc[4][4][4] (64 regs).
// One __syncthreads per k-tile; LDG of next tile overlaps compute of current.
// EPI: 0 = none, 1 = exact GELU, 2 = add residual R
template<int EPI>
__device__ __forceinline__
void gemm_body(const float* __restrict__ A, const float* __restrict__ B,
               const float* __restrict__ bias, const float* __restrict__ R,
               float* __restrict__ C, int M, int N, int K,
               int bx, int by,
               unsigned (*As)[128][20], unsigned (*Bs)[16][136])
{
    const int tid  = threadIdx.x;
    const int wid  = tid >> 5;
    const int lane = tid & 31;
    const int gid  = lane >> 2;   // 0..7
    const int tig  = lane & 3;    // 0..3
    const int warpM = (wid >> 2) * 64;   // 2 warps in m
    const int warpN = (wid & 3) * 32;    // 4 warps in n
    const int bm = by * 128;
    const int bn = bx * 128;

    float acc[4][4][4];
    #pragma unroll
    for (int mt = 0; mt < 4; mt++)
        #pragma unroll
        for (int nt = 0; nt < 4; nt++)
            #pragma unroll
            for (int r = 0; r < 4; r++) acc[mt][nt][r] = 0.f;

    int arow[2], ac4[2], brow[2], bc4[2];
    #pragma unroll
    for (int l = 0; l < 2; l++) {
        int f = tid + l * 256;
        arow[l] = f >> 2;  ac4[l] = (f & 3) * 4;    // A: 128 rows x 4 float4
        brow[l] = f >> 5;  bc4[l] = (f & 31) * 4;   // B: 16 rows x 32 float4
    }
    const float* Ablk = A + (long)bm * K;
    const float* Bblk = B + bn;

    float4 aS[2], bS[2];
    #pragma unroll
    for (int l = 0; l < 2; l++) {
        aS[l] = *(const float4*)&Ablk[(long)arow[l] * K + ac4[l]];
        bS[l] = *(const float4*)&Bblk[(long)brow[l] * N + bc4[l]];
    }
    #pragma unroll
    for (int l = 0; l < 2; l++) {
        *(uint4*)&As[0][arow[l]][ac4[l]] =
            make_uint4(f2tf32(aS[l].x), f2tf32(aS[l].y), f2tf32(aS[l].z), f2tf32(aS[l].w));
        *(uint4*)&Bs[0][brow[l]][bc4[l]] =
            make_uint4(f2tf32(bS[l].x), f2tf32(bS[l].y), f2tf32(bS[l].z), f2tf32(bS[l].w));
    }
    __syncthreads();

    int stage = 0;
    for (int k0 = 16; k0 <= K; k0 += 16) {
        const bool more = (k0 < K);
        if (more) {   // issue global loads for next tile early
            #pragma unroll
            for (int l = 0; l < 2; l++) {
                aS[l] = *(const float4*)&Ablk[(long)arow[l] * K + k0 + ac4[l]];
                bS[l] = *(const float4*)&Bblk[(long)(k0 + brow[l]) * N + bc4[l]];
            }
        }
        #pragma unroll
        for (int ks = 0; ks < 16; ks += 8) {
            unsigned af[4][4];
            #pragma unroll
            for (int mt = 0; mt < 4; mt++) {
                int r0 = warpM + mt * 16 + gid;
                af[mt][0] = As[stage][r0    ][ks + tig];
                af[mt][1] = As[stage][r0 + 8][ks + tig];
                af[mt][2] = As[stage][r0    ][ks + tig + 4];
                af[mt][3] = As[stage][r0 + 8][ks + tig + 4];
            }
            #pragma unroll
            for (int nt = 0; nt < 4; nt++) {
                int cc = warpN + nt * 8 + gid;
                unsigned b0 = Bs[stage][ks + tig    ][cc];
                unsigned b1 = Bs[stage][ks + tig + 4][cc];
                #pragma unroll
                for (int mt = 0; mt < 4; mt++)
                    mma_tf32(acc[mt][nt], af[mt], b0, b1);
            }
        }
        if (more) {   // store next tile into other stage, single barrier
            #pragma unroll
            for (int l = 0; l < 2; l++) {
                *(uint4*)&As[stage ^ 1][arow[l]][ac4[l]] =
                    make_uint4(f2tf32(aS[l].x), f2tf32(aS[l].y), f2tf32(aS[l].z), f2tf32(aS[l].w));
                *(uint4*)&Bs[stage ^ 1][brow[l]][bc4[l]] =
                    make_uint4(f2tf32(bS[l].x), f2tf32(bS[l].y), f2tf32(bS[l].z), f2tf32(bS[l].w));
            }
            __syncthreads();
            stage ^= 1;
        }
    }

    #pragma unroll
    for (int mt = 0; mt < 4; mt++) {
        int r0 = bm + warpM + mt * 16 + gid;
        #pragma unroll
        for (int nt = 0; nt < 4; nt++) {
            int c0 = bn + warpN + nt * 8 + tig * 2;
            float bv0 = bias[c0], bv1 = bias[c0 + 1];
            float v00 = acc[mt][nt][0] + bv0;
            float v01 = acc[mt][nt][1] + bv1;
            float v10 = acc[mt][nt][2] + bv0;
            float v11 = acc[mt][nt][3] + bv1;
            if (EPI == 1) {
                v00 = 0.5f * v00 * (1.f + erff(v00 * 0.70710678118654752f));
                v01 = 0.5f * v01 * (1.f + erff(v01 * 0.70710678118654752f));
                v10 = 0.5f * v10 * (1.f + erff(v10 * 0.70710678118654752f));
                v11 = 0.5f * v11 * (1.f + erff(v11 * 0.70710678118654752f));
            } else if (EPI == 2) {
                v00 += R[(long)r0 * N + c0];
                v01 += R[(long)r0 * N + c0 + 1];
                v10 += R[(long)(r0 + 8) * N + c0];
                v11 += R[(long)(r0 + 8) * N + c0 + 1];
            }
            *(float2*)&C[(long)r0 * N + c0]       = make_float2(v00, v01);
            *(float2*)&C[(long)(r0 + 8) * N + c0] = make_float2(v10, v11);
        }
    }
}

template<int EPI>
__global__ __launch_bounds__(256, 2)
void gemm_tf32(const float* __restrict__ A, const float* __restrict__ B,
               const float* __restrict__ bias, const float* __restrict__ R,
               float* __restrict__ C, int M, int N, int K)
{
    __shared__ unsigned As[2][128][20];
    __shared__ unsigned Bs[2][16][136];
    gemm_body<EPI>(A, B, bias, R, C, M, N, K, blockIdx.x, blockIdx.y, As, Bs);
}

// Fused QKV: blockIdx.z selects (W, bias, output); one launch, 3x CTAs.
__global__ __launch_bounds__(256, 2)
void gemm_qkv(const float* __restrict__ A,
              const float* __restrict__ Wq, const float* __restrict__ Wk, const float* __restrict__ Wv,
              const float* __restrict__ bq, const float* __restrict__ bk, const float* __restrict__ bv,
              float* __restrict__ Cq, float* __restrict__ Ck, float* __restrict__ Cv)
{
    __shared__ unsigned As[2][128][20];
    __shared__ unsigned Bs[2][16][136];
    const float* B  = (blockIdx.z == 0) ? Wq : (blockIdx.z == 1) ? Wk : Wv;
    const float* bi = (blockIdx.z == 0) ? bq : (blockIdx.z == 1) ? bk : bv;
    float*       C  = (blockIdx.z == 0) ? Cq : (blockIdx.z == 1) ? Ck : Cv;
    gemm_body<0>(A, B, bi, nullptr, C, ROWS, DD, DD, blockIdx.x, blockIdx.y, As, Bs);
}

// ---------------- Flash attention, tf32 tensor cores -------------------------
// BQ=64, BKV=64, HD=64. 128 threads (4 warps); warp w owns q-rows [w*16, w*16+16).
// Smem tiles padded to 72 cols: frag-load bank patterns 8*gid+tig / 8*tig+gid
// are conflict-free. grid: (S/64, B*H).
__global__ __launch_bounds__(128)
void attn_tc(const float* __restrict__ Q, const float* __restrict__ Km,
             const float* __restrict__ V, float* __restrict__ O)
{
    constexpr int PAD = 72;
    extern __shared__ unsigned smem[];
    unsigned* Qs = smem;               // [qrow][d]   64x72 tf32
    unsigned* Ks = Qs + 64 * PAD;      // [kvrow][d]  64x72 tf32
    unsigned* Vs = Ks + 64 * PAD;      // [kvrow][d]  64x72 tf32
    unsigned* Ps = Vs + 64 * PAD;      // [qrow][kv]  64x72 tf32

    const int tid  = threadIdx.x;
    const int wid  = tid >> 5;
    const int lane = tid & 31;
    const int gid  = lane >> 2;
    const int tig  = lane & 3;
    const int w16  = wid * 16;
    const int q0   = blockIdx.x * 64;
    const int b    = blockIdx.y / HH;
    const int h    = blockIdx.y % HH;
    const long headoff = (long)h * HD;
    const long rowbase = (long)b * SS;

    // load Q tile -> tf32 smem [row][d]
    #pragma unroll
    for (int l = 0; l < 8; l++) {
        int f   = tid + l * 128;       // 0..1023 float4s
        int row = f >> 4;
        int c4  = (f & 15) * 4;
        float4 a = *(const float4*)&Q[(rowbase + q0 + row) * DD + headoff + c4];
        *(uint4*)&Qs[row * PAD + c4] =
            make_uint4(f2tf32(a.x), f2tf32(a.y), f2tf32(a.z), f2tf32(a.w));
    }

    float m0 = -INFINITY, m1 = -INFINITY, l0 = 0.f, l1 = 0.f;
    float o[8][4];
    #pragma unroll
    for (int nt = 0; nt < 8; nt++)
        #pragma unroll
        for (int r = 0; r < 4; r++) o[nt][r] = 0.f;

    for (int t = 0; t < SS / 64; t++) {
        __syncthreads();               // all warps done with prev K/V tiles
        const int k0 = t * 64;
        #pragma unroll
        for (int l = 0; l < 8; l++) {
            int f   = tid + l * 128;
            int row = f >> 4;
            int c4  = (f & 15) * 4;
            float4 a = *(const float4*)&Km[(rowbase + k0 + row) * DD + headoff + c4];
            *(uint4*)&Ks[row * PAD + c4] =
                make_uint4(f2tf32(a.x), f2tf32(a.y), f2tf32(a.z), f2tf32(a.w));
            float4 vv = *(const float4*)&V[(rowbase + k0 + row) * DD + headoff + c4];
            *(uint4*)&Vs[row * PAD + c4] =
                make_uint4(f2tf32(vv.x), f2tf32(vv.y), f2tf32(vv.z), f2tf32(vv.w));
        }
        __syncthreads();

        // S = Q @ K^T : warp computes m16 x n64, k=64
        float sacc[8][4];
        #pragma unroll
        for (int nt = 0; nt < 8; nt++)
            #pragma unroll
            for (int r = 0; r < 4; r++) sacc[nt][r] = 0.f;
        #pragma unroll
        for (int kt = 0; kt < 8; kt++) {
            unsigned a[4];
            a[0] = Qs[(w16 + gid    ) * PAD + kt * 8 + tig];
            a[1] = Qs[(w16 + gid + 8) * PAD + kt * 8 + tig];
            a[2] = Qs[(w16 + gid    ) * PAD + kt * 8 + tig + 4];
            a[3] = Qs[(w16 + gid + 8) * PAD + kt * 8 + tig + 4];
            #pragma unroll
            for (int nt = 0; nt < 8; nt++) {
                unsigned b0 = Ks[(nt * 8 + gid) * PAD + kt * 8 + tig];
                unsigned b1 = Ks[(nt * 8 + gid) * PAD + kt * 8 + tig + 4];
                mma_tf32(sacc[nt], a, b0, b1);
            }
        }

        // online softmax: thread holds rows (w16+gid) [c0,c1] and (w16+gid+8) [c2,c3]
        float p[8][4];
        float rm0 = -INFINITY, rm1 = -INFINITY;
        #pragma unroll
        for (int nt = 0; nt < 8; nt++) {
            #pragma unroll
            for (int r = 0; r < 4; r++) p[nt][r] = sacc[nt][r] * 0.125f;  // 1/sqrt(64)
            rm0 = fmaxf(rm0, fmaxf(p[nt][0], p[nt][1]));
            rm1 = fmaxf(rm1, fmaxf(p[nt][2], p[nt][3]));
        }
        #pragma unroll
        for (int off = 1; off < 4; off <<= 1) {
            rm0 = fmaxf(rm0, __shfl_xor_sync(0xffffffffu, rm0, off));
            rm1 = fmaxf(rm1, __shfl_xor_sync(0xffffffffu, rm1, off));
        }
        float mn0 = fmaxf(m0, rm0), mn1 = fmaxf(m1, rm1);
        float corr0 = __expf(m0 - mn0), corr1 = __expf(m1 - mn1);
        m0 = mn0; m1 = mn1;
        float rs0 = 0.f, rs1 = 0.f;
        #pragma unroll
        for (int nt = 0; nt < 8; nt++) {
            p[nt][0] = __expf(p[nt][0] - mn0);
            p[nt][1] = __expf(p[nt][1] - mn0);
            p[nt][2] = __expf(p[nt][2] - mn1);
            p[nt][3] = __expf(p[nt][3] - mn1);
            rs0 += p[nt][0] + p[nt][1];
            rs1 += p[nt][2] + p[nt][3];
        }
        #pragma unroll
        for (int off = 1; off < 4; off <<= 1) {
            rs0 += __shfl_xor_sync(0xffffffffu, rs0, off);
            rs1 += __shfl_xor_sync(0xffffffffu, rs1, off);
        }
        l0 = l0 * corr0 + rs0;
        l1 = l1 * corr1 + rs1;
        #pragma unroll
        for (int nt = 0; nt < 8; nt++) {
            o[nt][0] *= corr0; o[nt][1] *= corr0;
            o[nt][2] *= corr1; o[nt][3] *= corr1;
        }

        // P -> smem (tf32); warp reads back only its OWN rows -> __syncwarp suffices
        #pragma unroll
        for (int nt = 0; nt < 8; nt++) {
            *(uint2*)&Ps[(w16 + gid    ) * PAD + nt * 8 + tig * 2] =
                make_uint2(f2tf32(p[nt][0]), f2tf32(p[nt][1]));
            *(uint2*)&Ps[(w16 + gid + 8) * PAD + nt * 8 + tig * 2] =
                make_uint2(f2tf32(p[nt][2]), f2tf32(p[nt][3]));
        }
        __syncwarp();

        // O += P @ V : A = P[m=q][k=kv], B = V[k=kv][n=d] (col-major = natural)
        #pragma unroll
        for (int kt = 0; kt < 8; kt++) {
            unsigned a[4];
            a[0] = Ps[(w16 + gid    ) * PAD + kt * 8 + tig];
            a[1] = Ps[(w16 + gid + 8) * PAD + kt * 8 + tig];
            a[2] = Ps[(w16 + gid    ) * PAD + kt * 8 + tig + 4];
            a[3] = Ps[(w16 + gid + 8) * PAD + kt * 8 + tig + 4];
            #pragma unroll
            for (int nt = 0; nt < 8; nt++) {
                unsigned b0 = Vs[(kt * 8 + tig    ) * PAD + nt * 8 + gid];
                unsigned b1 = Vs[(kt * 8 + tig + 4) * PAD + nt * 8 + gid];
                mma_tf32(o[nt], a, b0, b1);
            }
        }
        __syncwarp();   // P reads done before next iter's writes
    }

    // write O rows (w16+gid) and (w16+gid+8)
    const float inv0 = 1.f / l0, inv1 = 1.f / l1;
    const long r0 = rowbase + q0 + w16 + gid;
    #pragma unroll
    for (int nt = 0; nt < 8; nt++) {
        int c = nt * 8 + tig * 2;
        *(float2*)&O[r0 * DD + headoff + c] =
            make_float2(o[nt][0] * inv0, o[nt][1] * inv0);
        *(float2*)&O[(r0 + 8) * DD + headoff + c] =
            make_float2(o[nt][2] * inv1, o[nt][3] * inv1);
    }
}

// ---------------- launch -----------------------------------------------------
extern "C" void kernel_launch(void* const* d_in, const int* in_sizes, int n_in,
                              void* d_out, int out_size)
{
    const float* x   = (const float*)d_in[0];
    const float* Wq  = (const float*)d_in[1];
    const float* bq  = (const float*)d_in[2];
    const float* Wk  = (const float*)d_in[3];
    const float* bk  = (const float*)d_in[4];
    const float* Wv  = (const float*)d_in[5];
    const float* bv  = (const float*)d_in[6];
    const float* Wo  = (const float*)d_in[7];
    const float* bo  = (const float*)d_in[8];
    const float* W1  = (const float*)d_in[9];
    const float* b1  = (const float*)d_in[10];
    const float* W2  = (const float*)d_in[11];
    const float* b2  = (const float*)d_in[12];
    const float* g1  = (const float*)d_in[13];
    const float* be1 = (const float*)d_in[14];
    const float* g2  = (const float*)d_in[15];
    const float* be2 = (const float*)d_in[16];
    float* out = (float*)d_out;

    float *p_xn, *p_q, *p_k, *p_v, *p_att, *p_x1, *p_h;
    cudaGetSymbolAddress((void**)&p_xn,  g_xn);
    cudaGetSymbolAddress((void**)&p_q,   g_q);
    cudaGetSymbolAddress((void**)&p_k,   g_k);
    cudaGetSymbolAddress((void**)&p_v,   g_v);
    cudaGetSymbolAddress((void**)&p_att, g_att);
    cudaGetSymbolAddress((void**)&p_x1,  g_x1);
    cudaGetSymbolAddress((void**)&p_h,   g_h);

    const int attn_smem = 4 * 64 * 72 * (int)sizeof(unsigned);   // 73728 B
    cudaFuncSetAttribute(attn_tc, cudaFuncAttributeMaxDynamicSharedMemorySize, attn_smem);

    dim3 gemmDD(DD / 128, ROWS / 128);       // (8, 64)
    dim3 gemmDF(FF / 128, ROWS / 128);       // (32, 64)
    dim3 qkvGrid(DD / 128, ROWS / 128, 3);   // (8, 64, 3)

    // 1. LN1
    ln_kernel<<<ROWS, 256>>>(x, g1, be1, p_xn);
    // 2. fused QKV projections (tf32 tensor cores, one launch)
    gemm_qkv<<<qkvGrid, 256>>>(p_xn, Wq, Wk, Wv, bq, bk, bv, p_q, p_k, p_v);
    // 3. attention (tf32 tensor-core flash)
    dim3 attnGrid(SS / 64, BB * HH);     // (32, 64)
    attn_tc<<<attnGrid, 128, attn_smem>>>(p_q, p_k, p_v, p_att);
    // 4. output projection + residual
    gemm_tf32<2><<<gemmDD, 256>>>(p_att, Wo, bo, x, p_x1, ROWS, DD, DD);
    // 5. LN2
    ln_kernel<<<ROWS, 256>>>(p_x1, g2, be2, p_xn);
    // 6. FFN up + GELU
    gemm_tf32<1><<<gemmDF, 256>>>(p_xn, W1, b1, nullptr, p_h, ROWS, FF, DD);
    // 7. FFN down + residual -> out
    gemm_tf32<2><<<gemmDD, 256>>>(p_h, W2, b2, p_x1, out, ROWS, DD, FF);
}

// round 7
// speedup vs baseline: 1.6566x; 1.6291x over previous
#include <cuda_runtime.h>
#include <cuda_bf16.h>
#include <math.h>

// Problem constants
#define BB 4
#define SS 2048
#define DD 1024
#define HH 16
#define HD 64
#define FF 4096
#define ROWS (BB*SS)          // 8192

// ---------------- scratch (static device globals; no allocs allowed) ----------
__device__ float g_xn [ROWS*DD];
__device__ float g_q  [ROWS*DD];
__device__ float g_k  [ROWS*DD];
__device__ float g_v  [ROWS*DD];
__device__ float g_att[ROWS*DD];
__device__ float g_x1 [ROWS*DD];
__device__ float g_h  [ROWS*FF];

// ---------------- helpers -----------------------------------------------------
__device__ __forceinline__ unsigned pkbf(float lo, float hi) {
    __nv_bfloat162 h = __floats2bfloat162_rn(lo, hi);   // x=lo(low bits), y=hi
    return *reinterpret_cast<unsigned*>(&h);
}

// mma.m16n8k16 bf16 frag conventions (gid=lane>>2, tig=lane&3), each .b32 = 2 bf16
// along k (low = even k):
//   A: a0=A[gid][2tig..+1] a1=A[gid+8][..] a2=A[gid][8+2tig..+1] a3=A[gid+8][..]
//   B: b0=B[2tig..+1][gid] b1=B[8+2tig..+1][gid]
//   C: c0=C[gid][2tig] c1=C[gid][2tig+1] c2=C[gid+8][2tig] c3=C[gid+8][2tig+1]
__device__ __forceinline__ void mma_bf16(float* d, const unsigned* a, unsigned b0, unsigned b1) {
    asm volatile(
        "mma.sync.aligned.m16n8k16.row.col.f32.bf16.bf16.f32 "
        "{%0,%1,%2,%3}, {%4,%5,%6,%7}, {%8,%9}, {%0,%1,%2,%3};"
        : "+f"(d[0]), "+f"(d[1]), "+f"(d[2]), "+f"(d[3])
        : "r"(a[0]), "r"(a[1]), "r"(a[2]), "r"(a[3]), "r"(b0), "r"(b1));
}

// ---------------- LayerNorm: one block per row, 256 threads -------------------
__global__ __launch_bounds__(256)
void ln_kernel(const float* __restrict__ X, const float* __restrict__ g,
               const float* __restrict__ be, float* __restrict__ Y)
{
    int row = blockIdx.x;
    int tid = threadIdx.x;
    const float4 v = ((const float4*)(X + (long)row * DD))[tid];

    float s = v.x + v.y + v.z + v.w;
    float q = v.x*v.x + v.y*v.y + v.z*v.z + v.w*v.w;
    #pragma unroll
    for (int o = 16; o > 0; o >>= 1) {
        s += __shfl_xor_sync(0xffffffffu, s, o);
        q += __shfl_xor_sync(0xffffffffu, q, o);
    }
    __shared__ float ss[8], sq[8];
    int wid = tid >> 5, lane = tid & 31;
    if (lane == 0) { ss[wid] = s; sq[wid] = q; }
    __syncthreads();
    if (tid < 32) {
        float s2 = (tid < 8) ? ss[tid] : 0.f;
        float q2 = (tid < 8) ? sq[tid] : 0.f;
        #pragma unroll
        for (int o = 4; o > 0; o >>= 1) {
            s2 += __shfl_xor_sync(0xffffffffu, s2, o);
            q2 += __shfl_xor_sync(0xffffffffu, q2, o);
        }
        if (tid == 0) { ss[0] = s2; sq[0] = q2; }
    }
    __syncthreads();
    const float mean = ss[0] * (1.f / DD);
    const float var  = sq[0] * (1.f / DD) - mean * mean;
    const float rstd = rsqrtf(var + 1e-5f);

    const float4 gg = ((const float4*)g )[tid];
    const float4 bb = ((const float4*)be)[tid];
    float4 o4;
    o4.x = (v.x - mean) * rstd * gg.x + bb.x;
    o4.y = (v.y - mean) * rstd * gg.y + bb.y;
    o4.z = (v.z - mean) * rstd * gg.z + bb.z;
    o4.w = (v.w - mean) * rstd * gg.w + bb.w;
    ((float4*)(Y + (long)row * DD))[tid] = o4;
}

// ---------------- bf16 tensor-core GEMM body ---------------------------------
// 256 threads (8 warps), block tile 128x128, BK=16, double-buffered smem.
// Warp grid 2(m) x 4(n): warp tile 64x32. One m16n8k16 pass per BK tile.
// As: [m][6 kpairs pad 12] (12g+t spans 32 banks); Bs: [8 kpairs][128 n pad 136].
// EPI: 0 = none, 1 = exact GELU, 2 = add residual R
template<int EPI>
__device__ __forceinline__
void gemm_body(const float* __restrict__ A, const float* __restrict__ B,
               const float* __restrict__ bias, const float* __restrict__ R,
               float* __restrict__ C, int M, int N, int K,
               int bx, int by,
               unsigned (*As)[128][12], unsigned (*Bs)[8][136])
{
    const int tid  = threadIdx.x;
    const int wid  = tid >> 5;
    const int lane = tid & 31;
    const int gid  = lane >> 2;
    const int tig  = lane & 3;
    const int warpM = (wid >> 2) * 64;
    const int warpN = (wid & 3) * 32;
    const int bm = by * 128;
    const int bn = bx * 128;

    float acc[4][4][4];
    #pragma unroll
    for (int mt = 0; mt < 4; mt++)
        #pragma unroll
        for (int nt = 0; nt < 4; nt++)
            #pragma unroll
            for (int r = 0; r < 4; r++) acc[mt][nt][r] = 0.f;

    // A: 2 float4/thread; B: one k-row pair (2 float4) -> one uint4
    int arow[2], ac4[2];
    #pragma unroll
    for (int l = 0; l < 2; l++) {
        int f = tid + l * 256;
        arow[l] = f >> 2;  ac4[l] = (f & 3) * 4;
    }
    const int jB = tid >> 5;          // 0..7 k-pair row
    const int nB = (tid & 31) * 4;    // n offset
    const float* Ablk = A + (long)bm * K;
    const float* Bblk = B + bn;

    float4 aS[2], bLo, bHi;
    #pragma unroll
    for (int l = 0; l < 2; l++)
        aS[l] = *(const float4*)&Ablk[(long)arow[l] * K + ac4[l]];
    bLo = *(const float4*)&Bblk[(long)(2 * jB    ) * N + nB];
    bHi = *(const float4*)&Bblk[(long)(2 * jB + 1) * N + nB];

    #pragma unroll
    for (int l = 0; l < 2; l++)
        *(uint2*)&As[0][arow[l]][ac4[l] >> 1] =
            make_uint2(pkbf(aS[l].x, aS[l].y), pkbf(aS[l].z, aS[l].w));
    *(uint4*)&Bs[0][jB][nB] =
        make_uint4(pkbf(bLo.x, bHi.x), pkbf(bLo.y, bHi.y),
                   pkbf(bLo.z, bHi.z), pkbf(bLo.w, bHi.w));
    __syncthreads();

    int stage = 0;
    for (int k0 = 16; k0 <= K; k0 += 16) {
        const bool more = (k0 < K);
        if (more) {
            #pragma unroll
            for (int l = 0; l < 2; l++)
                aS[l] = *(const float4*)&Ablk[(long)arow[l] * K + k0 + ac4[l]];
            bLo = *(const float4*)&Bblk[(long)(k0 + 2 * jB    ) * N + nB];
            bHi = *(const float4*)&Bblk[(long)(k0 + 2 * jB + 1) * N + nB];
        }
        // single k16 pass
        unsigned af[4][4];
        #pragma unroll
        for (int mt = 0; mt < 4; mt++) {
            int r0 = warpM + mt * 16 + gid;
            af[mt][0] = As[stage][r0    ][tig];
            af[mt][1] = As[stage][r0 + 8][tig];
            af[mt][2] = As[stage][r0    ][tig + 4];
            af[mt][3] = As[stage][r0 + 8][tig + 4];
        }
        #pragma unroll
        for (int nt = 0; nt < 4; nt++) {
            int cc = warpN + nt * 8 + gid;
            unsigned b0 = Bs[stage][tig    ][cc];
            unsigned b1 = Bs[stage][tig + 4][cc];
            #pragma unroll
            for (int mt = 0; mt < 4; mt++)
                mma_bf16(acc[mt][nt], af[mt], b0, b1);
        }
        if (more) {
            #pragma unroll
            for (int l = 0; l < 2; l++)
                *(uint2*)&As[stage ^ 1][arow[l]][ac4[l] >> 1] =
                    make_uint2(pkbf(aS[l].x, aS[l].y), pkbf(aS[l].z, aS[l].w));
            *(uint4*)&Bs[stage ^ 1][jB][nB] =
                make_uint4(pkbf(bLo.x, bHi.x), pkbf(bLo.y, bHi.y),
                           pkbf(bLo.z, bHi.z), pkbf(bLo.w, bHi.w));
            __syncthreads();
            stage ^= 1;
        }
    }

    #pragma unroll
    for (int mt = 0; mt < 4; mt++) {
        int r0 = bm + warpM + mt * 16 + gid;
        #pragma unroll
        for (int nt = 0; nt < 4; nt++) {
            int c0 = bn + warpN + nt * 8 + tig * 2;
            float bv0 = bias[c0], bv1 = bias[c0 + 1];
            float v00 = acc[mt][nt][0] + bv0;
            float v01 = acc[mt][nt][1] + bv1;
            float v10 = acc[mt][nt][2] + bv0;
            float v11 = acc[mt][nt][3] + bv1;
            if (EPI == 1) {
                v00 = 0.5f * v00 * (1.f + erff(v00 * 0.70710678118654752f));
                v01 = 0.5f * v01 * (1.f + erff(v01 * 0.70710678118654752f));
                v10 = 0.5f * v10 * (1.f + erff(v10 * 0.70710678118654752f));
                v11 = 0.5f * v11 * (1.f + erff(v11 * 0.70710678118654752f));
            } else if (EPI == 2) {
                v00 += R[(long)r0 * N + c0];
                v01 += R[(long)r0 * N + c0 + 1];
                v10 += R[(long)(r0 + 8) * N + c0];
                v11 += R[(long)(r0 + 8) * N + c0 + 1];
            }
            *(float2*)&C[(long)r0 * N + c0]       = make_float2(v00, v01);
            *(float2*)&C[(long)(r0 + 8) * N + c0] = make_float2(v10, v11);
        }
    }
}

template<int EPI>
__global__ __launch_bounds__(256, 2)
void gemm_bf16k(const float* __restrict__ A, const float* __restrict__ B,
                const float* __restrict__ bias, const float* __restrict__ R,
                float* __restrict__ C, int M, int N, int K)
{
    __shared__ unsigned As[2][128][12];
    __shared__ unsigned Bs[2][8][136];
    gemm_body<EPI>(A, B, bias, R, C, M, N, K, blockIdx.x, blockIdx.y, As, Bs);
}

// Fused QKV: blockIdx.z selects (W, bias, output); one launch, 3x CTAs.
__global__ __launch_bounds__(256, 2)
void gemm_qkv(const float* __restrict__ A,
              const float* __restrict__ Wq, const float* __restrict__ Wk, const float* __restrict__ Wv,
              const float* __restrict__ bq, const float* __restrict__ bk, const float* __restrict__ bv,
              float* __restrict__ Cq, float* __restrict__ Ck, float* __restrict__ Cv)
{
    __shared__ unsigned As[2][128][12];
    __shared__ unsigned Bs[2][8][136];
    const float* B  = (blockIdx.z == 0) ? Wq : (blockIdx.z == 1) ? Wk : Wv;
    const float* bi = (blockIdx.z == 0) ? bq : (blockIdx.z == 1) ? bk : bv;
    float*       C  = (blockIdx.z == 0) ? Cq : (blockIdx.z == 1) ? Ck : Cv;
    gemm_body<0>(A, B, bi, nullptr, C, ROWS, DD, DD, blockIdx.x, blockIdx.y, As, Bs);
}

// ---------------- Flash attention, bf16 tensor cores -------------------------
// BQ=64, BKV=64, HD=64. 128 threads (4 warps); warp w owns q-rows [w*16, w*16+16).
// Layouts (uint = bf16x2):
//   Qs[64 qrow][32 dpair pad 36]   frag addr 4g+t  -> conflict-free
//   Ks[64 kvrow][32 dpair pad 36]  frag addr 4g+t  -> conflict-free
//   Vs[32 kvpair][64 d pad 72]     frag addr 8t+g  -> conflict-free
//   Ps[64 qrow][32 kvpair pad 36]  frag addr 4g+t  -> conflict-free
__global__ __launch_bounds__(128)
void attn_tc(const float* __restrict__ Q, const float* __restrict__ Km,
             const float* __restrict__ V, float* __restrict__ O)
{
    extern __shared__ unsigned smem[];
    unsigned* Qs = smem;               // 64*36
    unsigned* Ks = Qs + 64 * 36;       // 64*36
    unsigned* Vs = Ks + 64 * 36;       // 32*72
    unsigned* Ps = Vs + 32 * 72;       // 64*36

    const int tid  = threadIdx.x;
    const int wid  = tid >> 5;
    const int lane = tid & 31;
    const int gid  = lane >> 2;
    const int tig  = lane & 3;
    const int w16  = wid * 16;
    const int q0   = blockIdx.x * 64;
    const int b    = blockIdx.y / HH;
    const int h    = blockIdx.y % HH;
    const long headoff = (long)h * HD;
    const long rowbase = (long)b * SS;

    // load Q tile -> bf16x2 smem
    #pragma unroll
    for (int l = 0; l < 8; l++) {
        int f   = tid + l * 128;       // 0..1023 float4s
        int row = f >> 4;
        int c4  = (f & 15) * 4;
        float4 a = *(const float4*)&Q[(rowbase + q0 + row) * DD + headoff + c4];
        *(uint2*)&Qs[row * 36 + (c4 >> 1)] = make_uint2(pkbf(a.x, a.y), pkbf(a.z, a.w));
    }

    float m0 = -INFINITY, m1 = -INFINITY, l0 = 0.f, l1 = 0.f;
    float o[8][4];
    #pragma unroll
    for (int nt = 0; nt < 8; nt++)
        #pragma unroll
        for (int r = 0; r < 4; r++) o[nt][r] = 0.f;

    for (int t = 0; t < SS / 64; t++) {
        __syncthreads();
        const int k0 = t * 64;
        // K: pairs along d (contiguous)
        #pragma unroll
        for (int l = 0; l < 8; l++) {
            int f   = tid + l * 128;
            int row = f >> 4;
            int c4  = (f & 15) * 4;
            float4 a = *(const float4*)&Km[(rowbase + k0 + row) * DD + headoff + c4];
            *(uint2*)&Ks[row * 36 + (c4 >> 1)] = make_uint2(pkbf(a.x, a.y), pkbf(a.z, a.w));
        }
        // V: pairs along kv (across two rows)
        #pragma unroll
        for (int l = 0; l < 4; l++) {
            int f  = tid + l * 128;    // 0..511
            int j  = f >> 4;           // kv pair 0..31
            int d4 = (f & 15) * 4;
            float4 lo = *(const float4*)&V[(rowbase + k0 + 2 * j    ) * DD + headoff + d4];
            float4 hi = *(const float4*)&V[(rowbase + k0 + 2 * j + 1) * DD + headoff + d4];
            *(uint4*)&Vs[j * 72 + d4] =
                make_uint4(pkbf(lo.x, hi.x), pkbf(lo.y, hi.y), pkbf(lo.z, hi.z), pkbf(lo.w, hi.w));
        }
        __syncthreads();

        // S = Q @ K^T : warp m16 x n64, k=64 (4 k16 steps)
        float sacc[8][4];
        #pragma unroll
        for (int nt = 0; nt < 8; nt++)
            #pragma unroll
            for (int r = 0; r < 4; r++) sacc[nt][r] = 0.f;
        #pragma unroll
        for (int kt = 0; kt < 4; kt++) {
            unsigned a[4];
            a[0] = Qs[(w16 + gid    ) * 36 + kt * 8 + tig];
            a[1] = Qs[(w16 + gid + 8) * 36 + kt * 8 + tig];
            a[2] = Qs[(w16 + gid    ) * 36 + kt * 8 + tig + 4];
            a[3] = Qs[(w16 + gid + 8) * 36 + kt * 8 + tig + 4];
            #pragma unroll
            for (int nt = 0; nt < 8; nt++) {
                unsigned b0 = Ks[(nt * 8 + gid) * 36 + kt * 8 + tig];
                unsigned b1 = Ks[(nt * 8 + gid) * 36 + kt * 8 + tig + 4];
                mma_bf16(sacc[nt], a, b0, b1);
            }
        }

        // online softmax
        float p[8][4];
        float rm0 = -INFINITY, rm1 = -INFINITY;
        #pragma unroll
        for (int nt = 0; nt < 8; nt++) {
            #pragma unroll
            for (int r = 0; r < 4; r++) p[nt][r] = sacc[nt][r] * 0.125f;
            rm0 = fmaxf(rm0, fmaxf(p[nt][0], p[nt][1]));
            rm1 = fmaxf(rm1, fmaxf(p[nt][2], p[nt][3]));
        }
        #pragma unroll
        for (int off = 1; off < 4; off <<= 1) {
            rm0 = fmaxf(rm0, __shfl_xor_sync(0xffffffffu, rm0, off));
            rm1 = fmaxf(rm1, __shfl_xor_sync(0xffffffffu, rm1, off));
        }
        float mn0 = fmaxf(m0, rm0), mn1 = fmaxf(m1, rm1);
        float corr0 = __expf(m0 - mn0), corr1 = __expf(m1 - mn1);
        m0 = mn0; m1 = mn1;
        float rs0 = 0.f, rs1 = 0.f;
        #pragma unroll
        for (int nt = 0; nt < 8; nt++) {
            p[nt][0] = __expf(p[nt][0] - mn0);
            p[nt][1] = __expf(p[nt][1] - mn0);
            p[nt][2] = __expf(p[nt][2] - mn1);
            p[nt][3] = __expf(p[nt][3] - mn1);
            rs0 += p[nt][0] + p[nt][1];
            rs1 += p[nt][2] + p[nt][3];
        }
        #pragma unroll
        for (int off = 1; off < 4; off <<= 1) {
            rs0 += __shfl_xor_sync(0xffffffffu, rs0, off);
            rs1 += __shfl_xor_sync(0xffffffffu, rs1, off);
        }
        l0 = l0 * corr0 + rs0;
        l1 = l1 * corr1 + rs1;
        #pragma unroll
        for (int nt = 0; nt < 8; nt++) {
            o[nt][0] *= corr0; o[nt][1] *= corr0;
            o[nt][2] *= corr1; o[nt][3] *= corr1;
        }

        // P -> smem as bf16x2 kv-pairs; own rows only -> __syncwarp suffices
        #pragma unroll
        for (int nt = 0; nt < 8; nt++) {
            Ps[(w16 + gid    ) * 36 + nt * 4 + tig] = pkbf(p[nt][0], p[nt][1]);
            Ps[(w16 + gid + 8) * 36 + nt * 4 + tig] = pkbf(p[nt][2], p[nt][3]);
        }
        __syncwarp();

        // O += P @ V (4 k16 steps over kv)
        #pragma unroll
        for (int kt = 0; kt < 4; kt++) {
            unsigned a[4];
            a[0] = Ps[(w16 + gid    ) * 36 + kt * 8 + tig];
            a[1] = Ps[(w16 + gid + 8) * 36 + kt * 8 + tig];
            a[2] = Ps[(w16 + gid    ) * 36 + kt * 8 + tig + 4];
            a[3] = Ps[(w16 + gid + 8) * 36 + kt * 8 + tig + 4];
            #pragma unroll
            for (int nt = 0; nt < 8; nt++) {
                unsigned b0 = Vs[(kt * 8 + tig    ) * 72 + nt * 8 + gid];
                unsigned b1 = Vs[(kt * 8 + tig + 4) * 72 + nt * 8 + gid];
                mma_bf16(o[nt], a, b0, b1);
            }
        }
        __syncwarp();
    }

    const float inv0 = 1.f / l0, inv1 = 1.f / l1;
    const long r0 = rowbase + q0 + w16 + gid;
    #pragma unroll
    for (int nt = 0; nt < 8; nt++) {
        int c = nt * 8 + tig * 2;
        *(float2*)&O[r0 * DD + headoff + c] =
            make_float2(o[nt][0] * inv0, o[nt][1] * inv0);
        *(float2*)&O[(r0 + 8) * DD + headoff + c] =
            make_float2(o[nt][2] * inv1, o[nt][3] * inv1);
    }
}

// ---------------- launch -----------------------------------------------------
extern "C" void kernel_launch(void* const* d_in, const int* in_sizes, int n_in,
                              void* d_out, int out_size)
{
    const float* x   = (const float*)d_in[0];
    const float* Wq  = (const float*)d_in[1];
    const float* bq  = (const float*)d_in[2];
    const float* Wk  = (const float*)d_in[3];
    const float* bk  = (const float*)d_in[4];
    const float* Wv  = (const float*)d_in[5];
    const float* bv  = (const float*)d_in[6];
    const float* Wo  = (const float*)d_in[7];
    const float* bo  = (const float*)d_in[8];
    const float* W1  = (const float*)d_in[9];
    const float* b1  = (const float*)d_in[10];
    const float* W2  = (const float*)d_in[11];
    const float* b2  = (const float*)d_in[12];
    const float* g1  = (const float*)d_in[13];
    const float* be1 = (const float*)d_in[14];
    const float* g2  = (const float*)d_in[15];
    const float* be2 = (const float*)d_in[16];
    float* out = (float*)d_out;

    float *p_xn, *p_q, *p_k, *p_v, *p_att, *p_x1, *p_h;
    cudaGetSymbolAddress((void**)&p_xn,  g_xn);
    cudaGetSymbolAddress((void**)&p_q,   g_q);
    cudaGetSymbolAddress((void**)&p_k,   g_k);
    cudaGetSymbolAddress((void**)&p_v,   g_v);
    cudaGetSymbolAddress((void**)&p_att, g_att);
    cudaGetSymbolAddress((void**)&p_x1,  g_x1);
    cudaGetSymbolAddress((void**)&p_h,   g_h);

    const int attn_smem = (64*36 + 64*36 + 32*72 + 64*36) * (int)sizeof(unsigned); // 36864 B
    cudaFuncSetAttribute(attn_tc, cudaFuncAttributeMaxDynamicSharedMemorySize, attn_smem);

    dim3 gemmDD(DD / 128, ROWS / 128);       // (8, 64)
    dim3 gemmDF(FF / 128, ROWS / 128);       // (32, 64)
    dim3 qkvGrid(DD / 128, ROWS / 128, 3);   // (8, 64, 3)

    // 1. LN1
    ln_kernel<<<ROWS, 256>>>(x, g1, be1, p_xn);
    // 2. fused QKV projections (bf16 tensor cores, one launch)
    gemm_qkv<<<qkvGrid, 256>>>(p_xn, Wq, Wk, Wv, bq, bk, bv, p_q, p_k, p_v);
    // 3. attention (bf16 tensor-core flash)
    dim3 attnGrid(SS / 64, BB * HH);         // (32, 64)
    attn_tc<<<attnGrid, 128, attn_smem>>>(p_q, p_k, p_v, p_att);
    // 4. output projection + residual
    gemm_bf16k<2><<<gemmDD, 256>>>(p_att, Wo, bo, x, p_x1, ROWS, DD, DD);
    // 5. LN2
    ln_kernel<<<ROWS, 256>>>(p_x1, g2, be2, p_xn);
    // 6. FFN up + GELU
    gemm_bf16k<1><<<gemmDF, 256>>>(p_xn, W1, b1, nullptr, p_h, ROWS, FF, DD);
    // 7. FFN down + residual -> out
    gemm_bf16k<2><<<gemmDD, 256>>>(p_h, W2, b2, p_x1, out, ROWS, DD, FF);
}

// round 8
// speedup vs baseline: 1.7431x; 1.0522x over previous
#include <cuda_runtime.h>
#include <cuda_bf16.h>
#include <math.h>

// Problem constants
#define BB 4
#define SS 2048
#define DD 1024
#define HH 16
#define HD 64
#define FF 4096
#define ROWS (BB*SS)          // 8192
#define QS 3072               // packed QKV row stride

// ---------------- scratch (static device globals; no allocs allowed) ----------
__device__ __nv_bfloat16 g_xnb [ROWS*DD];     // LN output (bf16 A operand)
__device__ __nv_bfloat16 g_qkvb[ROWS*3*DD];   // QKV gemm output [row][3072]
__device__ __nv_bfloat16 g_attb[ROWS*DD];     // attention output
__device__ __nv_bfloat16 g_hb  [ROWS*FF];     // FFN hidden (post-GELU)
__device__ float         g_x1  [ROWS*DD];     // residual-1 (fp32)
__device__ unsigned g_wqkvp[(DD/2)*3*DD];     // k-paired bf16x2 weights
__device__ unsigned g_wop  [(DD/2)*DD];
__device__ unsigned g_w1p  [(DD/2)*FF];
__device__ unsigned g_w2p  [(FF/2)*DD];
__device__ float    g_bqkv [3*DD];

// ---------------- helpers -----------------------------------------------------
__device__ __forceinline__ unsigned pkbf(float lo, float hi) {
    __nv_bfloat162 h = __floats2bfloat162_rn(lo, hi);
    return *reinterpret_cast<unsigned*>(&h);
}

// mma.m16n8k16 bf16: frag conventions as before (gid=lane>>2, tig=lane&3)
__device__ __forceinline__ void mma_bf16(float* d, const unsigned* a, unsigned b0, unsigned b1) {
    asm volatile(
        "mma.sync.aligned.m16n8k16.row.col.f32.bf16.bf16.f32 "
        "{%0,%1,%2,%3}, {%4,%5,%6,%7}, {%8,%9}, {%0,%1,%2,%3};"
        : "+f"(d[0]), "+f"(d[1]), "+f"(d[2]), "+f"(d[3])
        : "r"(a[0]), "r"(a[1]), "r"(a[2]), "r"(a[3]), "r"(b0), "r"(b1));
}

// ---------------- weight packing (one-shot, cheap) ----------------------------
// P[j][n] = bf16x2( W[2j][n], W[2j+1][n] )  -- the GEMM's smem B layout
__global__ void pack_w(const float* __restrict__ W, unsigned* __restrict__ P,
                       int K, int N)
{
    int i = blockIdx.x * blockDim.x + threadIdx.x;
    int total = (K >> 1) * N;
    if (i >= total) return;
    int j = i / N, n = i - j * N;
    P[i] = pkbf(W[(long)(2*j) * N + n], W[(long)(2*j+1) * N + n]);
}

__global__ void pack_qkv(const float* __restrict__ Wq, const float* __restrict__ Wk,
                         const float* __restrict__ Wv,
                         const float* __restrict__ bq, const float* __restrict__ bk,
                         const float* __restrict__ bv,
                         unsigned* __restrict__ P, float* __restrict__ bcat)
{
    int i = blockIdx.x * blockDim.x + threadIdx.x;   // over (DD/2)*3*DD
    if (i >= (DD/2) * 3 * DD) return;
    int j = i / (3*DD), n = i - j * (3*DD);
    const float* W = (n < DD) ? Wq : (n < 2*DD) ? Wk : Wv;
    int col = (n < DD) ? n : (n < 2*DD) ? n - DD : n - 2*DD;
    P[i] = pkbf(W[(long)(2*j) * DD + col], W[(long)(2*j+1) * DD + col]);
    if (i < 3*DD) {
        const float* bb = (i < DD) ? bq : (i < 2*DD) ? bk : bv;
        int c = (i < DD) ? i : (i < 2*DD) ? i - DD : i - 2*DD;
        bcat[i] = bb[c];
    }
}

// ---------------- LayerNorm: fp32 in, bf16 out --------------------------------
__global__ __launch_bounds__(256)
void ln_kernel(const float* __restrict__ X, const float* __restrict__ g,
               const float* __restrict__ be, __nv_bfloat16* __restrict__ Y)
{
    int row = blockIdx.x;
    int tid = threadIdx.x;
    const float4 v = ((const float4*)(X + (long)row * DD))[tid];

    float s = v.x + v.y + v.z + v.w;
    float q = v.x*v.x + v.y*v.y + v.z*v.z + v.w*v.w;
    #pragma unroll
    for (int o = 16; o > 0; o >>= 1) {
        s += __shfl_xor_sync(0xffffffffu, s, o);
        q += __shfl_xor_sync(0xffffffffu, q, o);
    }
    __shared__ float ss[8], sq[8];
    int wid = tid >> 5, lane = tid & 31;
    if (lane == 0) { ss[wid] = s; sq[wid] = q; }
    __syncthreads();
    if (tid < 32) {
        float s2 = (tid < 8) ? ss[tid] : 0.f;
        float q2 = (tid < 8) ? sq[tid] : 0.f;
        #pragma unroll
        for (int o = 4; o > 0; o >>= 1) {
            s2 += __shfl_xor_sync(0xffffffffu, s2, o);
            q2 += __shfl_xor_sync(0xffffffffu, q2, o);
        }
        if (tid == 0) { ss[0] = s2; sq[0] = q2; }
    }
    __syncthreads();
    const float mean = ss[0] * (1.f / DD);
    const float var  = sq[0] * (1.f / DD) - mean * mean;
    const float rstd = rsqrtf(var + 1e-5f);

    const float4 gg = ((const float4*)g )[tid];
    const float4 bb = ((const float4*)be)[tid];
    float ox = (v.x - mean) * rstd * gg.x + bb.x;
    float oy = (v.y - mean) * rstd * gg.y + bb.y;
    float oz = (v.z - mean) * rstd * gg.z + bb.z;
    float ow = (v.w - mean) * rstd * gg.w + bb.w;
    uint2 o2 = make_uint2(pkbf(ox, oy), pkbf(oz, ow));
    *(uint2*)&Y[(long)row * DD + tid * 4] = o2;
}

// ---------------- bf16 tensor-core GEMM --------------------------------------
// CTA tile 128x256, BK=16, 256 threads (8 warps of 64x64), double-buffered.
// A: [M][K] bf16 row-major. Bp: [K/2][N] k-paired bf16x2 (pre-packed weights).
// As[128][12] (pad 12 -> frag 12g+t conflict-free); Bs[8][264] (pad 264 -> 8t+g).
// EPI: 0 = bias, out bf16; 1 = bias+GELU, out bf16; 2 = bias+residual, out fp32.
template<int EPI>
__global__ __launch_bounds__(256, 1)
void gemm_bf16(const __nv_bfloat16* __restrict__ A, const unsigned* __restrict__ Bp,
               const float* __restrict__ bias, const float* __restrict__ R,
               void* __restrict__ Cout, int M, int N, int K)
{
    __shared__ unsigned As[2][128][12];
    __shared__ unsigned Bs[2][8][264];

    const int tid  = threadIdx.x;
    const int wid  = tid >> 5;
    const int lane = tid & 31;
    const int gid  = lane >> 2;
    const int tig  = lane & 3;
    const int warpM = (wid >> 2) * 64;   // 2 warps in m
    const int warpN = (wid & 3) * 64;    // 4 warps in n
    const long bm = (long)blockIdx.y * 128;
    const long bn = (long)blockIdx.x * 256;

    float acc[4][8][4];
    #pragma unroll
    for (int mt = 0; mt < 4; mt++)
        #pragma unroll
        for (int nt = 0; nt < 8; nt++)
            #pragma unroll
            for (int r = 0; r < 4; r++) acc[mt][nt][r] = 0.f;

    // A loader: row = tid&127, half = tid>>7 (one uint4 = 8 bf16 along k)
    const int arow = tid & 127, ahalf = tid >> 7;
    const __nv_bfloat16* Asrc = A + (bm + arow) * K + ahalf * 8;
    // B loader: j = tid>>5 (kpair row), strided uint2 chunks (conflict-free STS)
    const int bj = tid >> 5, bl = tid & 31;
    const unsigned* Bsrc = Bp + (long)bj * N + bn;

    uint4 av;
    uint2 bv[4];
    av = *(const uint4*)&Asrc[0];
    #pragma unroll
    for (int p = 0; p < 4; p++)
        bv[p] = *(const uint2*)&Bsrc[2 * (bl + 32 * p)];
    *(uint4*)&As[0][arow][ahalf * 4] = av;
    #pragma unroll
    for (int p = 0; p < 4; p++)
        *(uint2*)&Bs[0][bj][2 * (bl + 32 * p)] = bv[p];
    __syncthreads();

    int stage = 0;
    for (int k0 = 16; k0 <= K; k0 += 16) {
        const bool more = (k0 < K);
        if (more) {
            av = *(const uint4*)&Asrc[k0];
            const unsigned* bsrc = Bsrc + (long)(k0 >> 1) * N;
            #pragma unroll
            for (int p = 0; p < 4; p++)
                bv[p] = *(const uint2*)&bsrc[2 * (bl + 32 * p)];
        }
        // fragments
        unsigned af[4][4];
        #pragma unroll
        for (int mt = 0; mt < 4; mt++) {
            int r0 = warpM + mt * 16 + gid;
            af[mt][0] = As[stage][r0    ][tig];
            af[mt][1] = As[stage][r0 + 8][tig];
            af[mt][2] = As[stage][r0    ][tig + 4];
            af[mt][3] = As[stage][r0 + 8][tig + 4];
        }
        #pragma unroll
        for (int nt = 0; nt < 8; nt++) {
            int cc = warpN + nt * 8 + gid;
            unsigned b0 = Bs[stage][tig    ][cc];
            unsigned b1 = Bs[stage][tig + 4][cc];
            #pragma unroll
            for (int mt = 0; mt < 4; mt++)
                mma_bf16(acc[mt][nt], af[mt], b0, b1);
        }
        if (more) {
            *(uint4*)&As[stage ^ 1][arow][ahalf * 4] = av;
            #pragma unroll
            for (int p = 0; p < 4; p++)
                *(uint2*)&Bs[stage ^ 1][bj][2 * (bl + 32 * p)] = bv[p];
            __syncthreads();
            stage ^= 1;
        }
    }

    // epilogue
    #pragma unroll
    for (int mt = 0; mt < 4; mt++) {
        long r0 = bm + warpM + mt * 16 + gid;
        #pragma unroll
        for (int nt = 0; nt < 8; nt++) {
            long c0 = bn + warpN + nt * 8 + tig * 2;
            float bv0 = bias[c0], bv1 = bias[c0 + 1];
            float v00 = acc[mt][nt][0] + bv0;
            float v01 = acc[mt][nt][1] + bv1;
            float v10 = acc[mt][nt][2] + bv0;
            float v11 = acc[mt][nt][3] + bv1;
            if (EPI == 1) {
                v00 = 0.5f * v00 * (1.f + erff(v00 * 0.70710678118654752f));
                v01 = 0.5f * v01 * (1.f + erff(v01 * 0.70710678118654752f));
                v10 = 0.5f * v10 * (1.f + erff(v10 * 0.70710678118654752f));
                v11 = 0.5f * v11 * (1.f + erff(v11 * 0.70710678118654752f));
            } else if (EPI == 2) {
                v00 += R[r0 * N + c0];
                v01 += R[r0 * N + c0 + 1];
                v10 += R[(r0 + 8) * N + c0];
                v11 += R[(r0 + 8) * N + c0 + 1];
            }
            if (EPI == 2) {
                float* C = (float*)Cout;
                *(float2*)&C[r0 * N + c0]       = make_float2(v00, v01);
                *(float2*)&C[(r0 + 8) * N + c0] = make_float2(v10, v11);
            } else {
                __nv_bfloat16* C = (__nv_bfloat16*)Cout;
                *(unsigned*)&C[r0 * N + c0]       = pkbf(v00, v01);
                *(unsigned*)&C[(r0 + 8) * N + c0] = pkbf(v10, v11);
            }
        }
    }
}

// ---------------- Flash attention, bf16 tensor cores -------------------------
// Reads Q/K/V from the packed QKV gemm output (stride QS), writes bf16 att.
__global__ __launch_bounds__(128)
void attn_tc(const __nv_bfloat16* __restrict__ QKV, __nv_bfloat16* __restrict__ O)
{
    extern __shared__ unsigned smem[];
    unsigned* Qs = smem;               // [64 qrow][32 dpair pad 36]
    unsigned* Ks = Qs + 64 * 36;       // [64 kvrow][32 dpair pad 36]
    unsigned* Vs = Ks + 64 * 36;       // [32 kvpair][64 d pad 72]
    unsigned* Ps = Vs + 32 * 72;       // [64 qrow][32 kvpair pad 36]

    const int tid  = threadIdx.x;
    const int wid  = tid >> 5;
    const int lane = tid & 31;
    const int gid  = lane >> 2;
    const int tig  = lane & 3;
    const int w16  = wid * 16;
    const int q0   = blockIdx.x * 64;
    const int b    = blockIdx.y / HH;
    const int h    = blockIdx.y % HH;
    const long hq  = (long)h * HD;           // Q offset in packed row
    const long hk  = hq + DD;                // K offset
    const long hv  = hq + 2 * DD;            // V offset
    const long rowbase = (long)b * SS;

    // Q tile: 64 rows x 64 d, uint4 = 8 bf16 (dpairs contiguous)
    #pragma unroll
    for (int l = 0; l < 4; l++) {
        int f   = tid + l * 128;       // 0..511
        int row = f >> 3;
        int c   = f & 7;
        uint4 v = *(const uint4*)&QKV[(rowbase + q0 + row) * QS + hq + c * 8];
        *(uint4*)&Qs[row * 36 + c * 4] = v;
    }

    float m0 = -INFINITY, m1 = -INFINITY, l0 = 0.f, l1 = 0.f;
    float o[8][4];
    #pragma unroll
    for (int nt = 0; nt < 8; nt++)
        #pragma unroll
        for (int r = 0; r < 4; r++) o[nt][r] = 0.f;

    for (int t = 0; t < SS / 64; t++) {
        __syncthreads();
        const int k0 = t * 64;
        #pragma unroll
        for (int l = 0; l < 4; l++) {
            int f   = tid + l * 128;
            int row = f >> 3;
            int c   = f & 7;
            uint4 v = *(const uint4*)&QKV[(rowbase + k0 + row) * QS + hk + c * 8];
            *(uint4*)&Ks[row * 36 + c * 4] = v;
        }
        // V: kv-pairs interleaved from two consecutive rows
        #pragma unroll
        for (int l = 0; l < 2; l++) {
            int f = tid + l * 128;     // 0..255
            int j = f >> 3;            // kv pair 0..31
            int c = f & 7;
            uint4 lo = *(const uint4*)&QKV[(rowbase + k0 + 2*j    ) * QS + hv + c * 8];
            uint4 hi = *(const uint4*)&QKV[(rowbase + k0 + 2*j + 1) * QS + hv + c * 8];
            uint4 o0, o1;
            o0.x = __byte_perm(lo.x, hi.x, 0x5410); o0.y = __byte_perm(lo.x, hi.x, 0x7632);
            o0.z = __byte_perm(lo.y, hi.y, 0x5410); o0.w = __byte_perm(lo.y, hi.y, 0x7632);
            o1.x = __byte_perm(lo.z, hi.z, 0x5410); o1.y = __byte_perm(lo.z, hi.z, 0x7632);
            o1.z = __byte_perm(lo.w, hi.w, 0x5410); o1.w = __byte_perm(lo.w, hi.w, 0x7632);
            *(uint4*)&Vs[j * 72 + c * 8]     = o0;
            *(uint4*)&Vs[j * 72 + c * 8 + 4] = o1;
        }
        __syncthreads();

        // S = Q @ K^T (4 k16 steps over d)
        float sacc[8][4];
        #pragma unroll
        for (int nt = 0; nt < 8; nt++)
            #pragma unroll
            for (int r = 0; r < 4; r++) sacc[nt][r] = 0.f;
        #pragma unroll
        for (int kt = 0; kt < 4; kt++) {
            unsigned a[4];
            a[0] = Qs[(w16 + gid    ) * 36 + kt * 8 + tig];
            a[1] = Qs[(w16 + gid + 8) * 36 + kt * 8 + tig];
            a[2] = Qs[(w16 + gid    ) * 36 + kt * 8 + tig + 4];
            a[3] = Qs[(w16 + gid + 8) * 36 + kt * 8 + tig + 4];
            #pragma unroll
            for (int nt = 0; nt < 8; nt++) {
                unsigned b0 = Ks[(nt * 8 + gid) * 36 + kt * 8 + tig];
                unsigned b1 = Ks[(nt * 8 + gid) * 36 + kt * 8 + tig + 4];
                mma_bf16(sacc[nt], a, b0, b1);
            }
        }

        // online softmax
        float p[8][4];
        float rm0 = -INFINITY, rm1 = -INFINITY;
        #pragma unroll
        for (int nt = 0; nt < 8; nt++) {
            #pragma unroll
            for (int r = 0; r < 4; r++) p[nt][r] = sacc[nt][r] * 0.125f;
            rm0 = fmaxf(rm0, fmaxf(p[nt][0], p[nt][1]));
            rm1 = fmaxf(rm1, fmaxf(p[nt][2], p[nt][3]));
        }
        #pragma unroll
        for (int off = 1; off < 4; off <<= 1) {
            rm0 = fmaxf(rm0, __shfl_xor_sync(0xffffffffu, rm0, off));
            rm1 = fmaxf(rm1, __shfl_xor_sync(0xffffffffu, rm1, off));
        }
        float mn0 = fmaxf(m0, rm0), mn1 = fmaxf(m1, rm1);
        float corr0 = __expf(m0 - mn0), corr1 = __expf(m1 - mn1);
        m0 = mn0; m1 = mn1;
        float rs0 = 0.f, rs1 = 0.f;
        #pragma unroll
        for (int nt = 0; nt < 8; nt++) {
            p[nt][0] = __expf(p[nt][0] - mn0);
            p[nt][1] = __expf(p[nt][1] - mn0);
            p[nt][2] = __expf(p[nt][2] - mn1);
            p[nt][3] = __expf(p[nt][3] - mn1);
            rs0 += p[nt][0] + p[nt][1];
            rs1 += p[nt][2] + p[nt][3];
        }
        #pragma unroll
        for (int off = 1; off < 4; off <<= 1) {
            rs0 += __shfl_xor_sync(0xffffffffu, rs0, off);
            rs1 += __shfl_xor_sync(0xffffffffu, rs1, off);
        }
        l0 = l0 * corr0 + rs0;
        l1 = l1 * corr1 + rs1;
        #pragma unroll
        for (int nt = 0; nt < 8; nt++) {
            o[nt][0] *= corr0; o[nt][1] *= corr0;
            o[nt][2] *= corr1; o[nt][3] *= corr1;
        }

        // P -> smem bf16x2 (own rows only)
        #pragma unroll
        for (int nt = 0; nt < 8; nt++) {
            Ps[(w16 + gid    ) * 36 + nt * 4 + tig] = pkbf(p[nt][0], p[nt][1]);
            Ps[(w16 + gid + 8) * 36 + nt * 4 + tig] = pkbf(p[nt][2], p[nt][3]);
        }
        __syncwarp();

        // O += P @ V
        #pragma unroll
        for (int kt = 0; kt < 4; kt++) {
            unsigned a[4];
            a[0] = Ps[(w16 + gid    ) * 36 + kt * 8 + tig];
            a[1] = Ps[(w16 + gid + 8) * 36 + kt * 8 + tig];
            a[2] = Ps[(w16 + gid    ) * 36 + kt * 8 + tig + 4];
            a[3] = Ps[(w16 + gid + 8) * 36 + kt * 8 + tig + 4];
            #pragma unroll
            for (int nt = 0; nt < 8; nt++) {
                unsigned b0 = Vs[(kt * 8 + tig    ) * 72 + nt * 8 + gid];
                unsigned b1 = Vs[(kt * 8 + tig + 4) * 72 + nt * 8 + gid];
                mma_bf16(o[nt], a, b0, b1);
            }
        }
        __syncwarp();
    }

    const float inv0 = 1.f / l0, inv1 = 1.f / l1;
    const long r0 = rowbase + q0 + w16 + gid;
    #pragma unroll
    for (int nt = 0; nt < 8; nt++) {
        long c = (long)h * HD + nt * 8 + tig * 2;
        *(unsigned*)&O[r0 * DD + c]       = pkbf(o[nt][0] * inv0, o[nt][1] * inv0);
        *(unsigned*)&O[(r0 + 8) * DD + c] = pkbf(o[nt][2] * inv1, o[nt][3] * inv1);
    }
}

// ---------------- launch -----------------------------------------------------
extern "C" void kernel_launch(void* const* d_in, const int* in_sizes, int n_in,
                              void* d_out, int out_size)
{
    const float* x   = (const float*)d_in[0];
    const float* Wq  = (const float*)d_in[1];
    const float* bq  = (const float*)d_in[2];
    const float* Wk  = (const float*)d_in[3];
    const float* bk  = (const float*)d_in[4];
    const float* Wv  = (const float*)d_in[5];
    const float* bv  = (const float*)d_in[6];
    const float* Wo  = (const float*)d_in[7];
    const float* bo  = (const float*)d_in[8];
    const float* W1  = (const float*)d_in[9];
    const float* b1  = (const float*)d_in[10];
    const float* W2  = (const float*)d_in[11];
    const float* b2  = (const float*)d_in[12];
    const float* g1  = (const float*)d_in[13];
    const float* be1 = (const float*)d_in[14];
    const float* g2  = (const float*)d_in[15];
    const float* be2 = (const float*)d_in[16];
    float* out = (float*)d_out;

    __nv_bfloat16 *p_xnb, *p_qkvb, *p_attb, *p_hb;
    float *p_x1, *p_bqkv;
    unsigned *p_wqkvp, *p_wop, *p_w1p, *p_w2p;
    cudaGetSymbolAddress((void**)&p_xnb,   g_xnb);
    cudaGetSymbolAddress((void**)&p_qkvb,  g_qkvb);
    cudaGetSymbolAddress((void**)&p_attb,  g_attb);
    cudaGetSymbolAddress((void**)&p_hb,    g_hb);
    cudaGetSymbolAddress((void**)&p_x1,    g_x1);
    cudaGetSymbolAddress((void**)&p_wqkvp, g_wqkvp);
    cudaGetSymbolAddress((void**)&p_wop,   g_wop);
    cudaGetSymbolAddress((void**)&p_w1p,   g_w1p);
    cudaGetSymbolAddress((void**)&p_w2p,   g_w2p);
    cudaGetSymbolAddress((void**)&p_bqkv,  g_bqkv);

    const int attn_smem = (64*36 + 64*36 + 32*72 + 64*36) * (int)sizeof(unsigned); // 36864 B
    cudaFuncSetAttribute(attn_tc, cudaFuncAttributeMaxDynamicSharedMemorySize, attn_smem);

    // 0. pack weights to bf16 (k-paired layout)
    pack_qkv<<<((DD/2)*3*DD + 255)/256, 256>>>(Wq, Wk, Wv, bq, bk, bv, p_wqkvp, p_bqkv);
    pack_w<<<((DD/2)*DD + 255)/256, 256>>>(Wo, p_wop, DD, DD);
    pack_w<<<((DD/2)*FF + 255)/256, 256>>>(W1, p_w1p, DD, FF);
    pack_w<<<((FF/2)*DD + 255)/256, 256>>>(W2, p_w2p, FF, DD);

    // 1. LN1 -> bf16
    ln_kernel<<<ROWS, 256>>>(x, g1, be1, p_xnb);
    // 2. fused QKV projection: one GEMM, N=3072
    dim3 qkvGrid(3*DD/256, ROWS/128);        // (12, 64)
    gemm_bf16<0><<<qkvGrid, 256>>>(p_xnb, p_wqkvp, p_bqkv, nullptr, p_qkvb, ROWS, 3*DD, DD);
    // 3. attention
    dim3 attnGrid(SS/64, BB*HH);             // (32, 64)
    attn_tc<<<attnGrid, 128, attn_smem>>>(p_qkvb, p_attb);
    // 4. output projection + residual (fp32 out)
    dim3 gridDD(DD/256, ROWS/128);           // (4, 64)
    gemm_bf16<2><<<gridDD, 256>>>(p_attb, p_wop, bo, x, p_x1, ROWS, DD, DD);
    // 5. LN2 -> bf16
    ln_kernel<<<ROWS, 256>>>(p_x1, g2, be2, p_xnb);
    // 6. FFN up + GELU -> bf16
    dim3 gridDF(FF/256, ROWS/128);           // (16, 64)
    gemm_bf16<1><<<gridDF, 256>>>(p_xnb, p_w1p, b1, nullptr, p_hb, ROWS, FF, DD);
    // 7. FFN down + residual -> out (fp32)
    gemm_bf16<2><<<gridDD, 256>>>(p_hb, p_w2p, b2, p_x1, out, ROWS, DD, FF);
}

// round 10
// speedup vs baseline: 1.8517x; 1.0623x over previous
#include <cuda_runtime.h>
#include <cuda_bf16.h>
#include <math.h>

// Problem constants
#define BB 4
#define SS 2048
#define DD 1024
#define HH 16
#define HD 64
#define FF 4096
#define ROWS (BB*SS)          // 8192
#define QS 3072               // packed QKV row stride

// ---------------- scratch (static device globals; no allocs allowed) ----------
__device__ __nv_bfloat16 g_xnb [ROWS*DD];
__device__ __nv_bfloat16 g_qkvb[ROWS*3*DD];
__device__ __nv_bfloat16 g_attb[ROWS*DD];
__device__ __nv_bfloat16 g_hb  [ROWS*FF];
__device__ float         g_x1  [ROWS*DD];
__device__ unsigned g_wqkvp[(DD/2)*3*DD];
__device__ unsigned g_wop  [(DD/2)*DD];
__device__ unsigned g_w1p  [(DD/2)*FF];
__device__ unsigned g_w2p  [(FF/2)*DD];
__device__ float    g_bqkv [3*DD];

// ---------------- helpers -----------------------------------------------------
__device__ __forceinline__ unsigned pkbf(float lo, float hi) {
    __nv_bfloat162 h = __floats2bfloat162_rn(lo, hi);
    return *reinterpret_cast<unsigned*>(&h);
}

__device__ __forceinline__ void mma_bf16(float* d, const unsigned* a, unsigned b0, unsigned b1) {
    asm volatile(
        "mma.sync.aligned.m16n8k16.row.col.f32.bf16.bf16.f32 "
        "{%0,%1,%2,%3}, {%4,%5,%6,%7}, {%8,%9}, {%0,%1,%2,%3};"
        : "+f"(d[0]), "+f"(d[1]), "+f"(d[2]), "+f"(d[3])
        : "r"(a[0]), "r"(a[1]), "r"(a[2]), "r"(a[3]), "r"(b0), "r"(b1));
}

__device__ __forceinline__ void cp16(void* dst, const void* src) {
    unsigned d = (unsigned)__cvta_generic_to_shared(dst);
    asm volatile("cp.async.ca.shared.global [%0], [%1], 16;\n" :: "r"(d), "l"(src));
}
__device__ __forceinline__ void cp8(void* dst, const void* src) {
    unsigned d = (unsigned)__cvta_generic_to_shared(dst);
    asm volatile("cp.async.ca.shared.global [%0], [%1], 8;\n" :: "r"(d), "l"(src));
}

// ---------------- weight packing (one-shot, cheap) ----------------------------
__global__ void pack_w(const float* __restrict__ W, unsigned* __restrict__ P,
                       int K, int N)
{
    int i = blockIdx.x * blockDim.x + threadIdx.x;
    int total = (K >> 1) * N;
    if (i >= total) return;
    int j = i / N, n = i - j * N;
    P[i] = pkbf(W[(long)(2*j) * N + n], W[(long)(2*j+1) * N + n]);
}

__global__ void pack_qkv(const float* __restrict__ Wq, const float* __restrict__ Wk,
                         const float* __restrict__ Wv,
                         const float* __restrict__ bq, const float* __restrict__ bk,
                         const float* __restrict__ bv,
                         unsigned* __restrict__ P, float* __restrict__ bcat)
{
    int i = blockIdx.x * blockDim.x + threadIdx.x;
    if (i >= (DD/2) * 3 * DD) return;
    int j = i / (3*DD), n = i - j * (3*DD);
    const float* W = (n < DD) ? Wq : (n < 2*DD) ? Wk : Wv;
    int col = (n < DD) ? n : (n < 2*DD) ? n - DD : n - 2*DD;
    P[i] = pkbf(W[(long)(2*j) * DD + col], W[(long)(2*j+1) * DD + col]);
    if (i < 3*DD) {
        const float* bb = (i < DD) ? bq : (i < 2*DD) ? bk : bv;
        int c = (i < DD) ? i : (i < 2*DD) ? i - DD : i - 2*DD;
        bcat[i] = bb[c];
    }
}

// ---------------- LayerNorm: fp32 in, bf16 out --------------------------------
__global__ __launch_bounds__(256)
void ln_kernel(const float* __restrict__ X, const float* __restrict__ g,
               const float* __restrict__ be, __nv_bfloat16* __restrict__ Y)
{
    int row = blockIdx.x;
    int tid = threadIdx.x;
    const float4 v = ((const float4*)(X + (long)row * DD))[tid];

    float s = v.x + v.y + v.z + v.w;
    float q = v.x*v.x + v.y*v.y + v.z*v.z + v.w*v.w;
    #pragma unroll
    for (int o = 16; o > 0; o >>= 1) {
        s += __shfl_xor_sync(0xffffffffu, s, o);
        q += __shfl_xor_sync(0xffffffffu, q, o);
    }
    __shared__ float ss[8], sq[8];
    int wid = tid >> 5, lane = tid & 31;
    if (lane == 0) { ss[wid] = s; sq[wid] = q; }
    __syncthreads();
    if (tid < 32) {
        float s2 = (tid < 8) ? ss[tid] : 0.f;
        float q2 = (tid < 8) ? sq[tid] : 0.f;
        #pragma unroll
        for (int o = 4; o > 0; o >>= 1) {
            s2 += __shfl_xor_sync(0xffffffffu, s2, o);
            q2 += __shfl_xor_sync(0xffffffffu, q2, o);
        }
        if (tid == 0) { ss[0] = s2; sq[0] = q2; }
    }
    __syncthreads();
    const float mean = ss[0] * (1.f / DD);
    const float var  = sq[0] * (1.f / DD) - mean * mean;
    const float rstd = rsqrtf(var + 1e-5f);

    const float4 gg = ((const float4*)g )[tid];
    const float4 bb = ((const float4*)be)[tid];
    float ox = (v.x - mean) * rstd * gg.x + bb.x;
    float oy = (v.y - mean) * rstd * gg.y + bb.y;
    float oz = (v.z - mean) * rstd * gg.z + bb.z;
    float ow = (v.w - mean) * rstd * gg.w + bb.w;
    uint2 o2 = make_uint2(pkbf(ox, oy), pkbf(oz, ow));
    *(uint2*)&Y[(long)row * DD + tid * 4] = o2;
}

// ---------------- bf16 tensor-core GEMM, 3-stage cp.async pipeline ------------
// CTA tile 128x256, BK=16, 256 threads (8 warps of 64x64).
// A: [M][K] bf16 row-major. Bp: [K/2][N] k-paired bf16x2 (pre-packed).
// As[128][12] (frag 12g+t conflict-free); Bs[8][264] (frag 8t+g conflict-free).
// EPI: 0 = bias->bf16; 1 = bias+GELU->bf16; 2 = bias+residual->fp32.
template<int EPI>
__global__ __launch_bounds__(256, 1)
void gemm_bf16(const __nv_bfloat16* __restrict__ A, const unsigned* __restrict__ Bp,
               const float* __restrict__ bias, const float* __restrict__ R,
               void* __restrict__ Cout, int M, int N, int K)
{
    __shared__ unsigned As[3][128][12];
    __shared__ unsigned Bs[3][8][264];

    const int tid  = threadIdx.x;
    const int wid  = tid >> 5;
    const int lane = tid & 31;
    const int gid  = lane >> 2;
    const int tig  = lane & 3;
    const int warpM = (wid >> 2) * 64;
    const int warpN = (wid & 3) * 64;
    const long bm = (long)blockIdx.y * 128;
    const long bn = (long)blockIdx.x * 256;

    float acc[4][8][4];
    #pragma unroll
    for (int mt = 0; mt < 4; mt++)
        #pragma unroll
        for (int nt = 0; nt < 8; nt++)
            #pragma unroll
            for (int r = 0; r < 4; r++) acc[mt][nt][r] = 0.f;

    const int arow = tid & 127, ahalf = tid >> 7;
    const __nv_bfloat16* Asrc = A + (bm + arow) * K + ahalf * 8;
    const int bj = tid >> 5, bl = tid & 31;
    const unsigned* Bsrc = Bp + (long)bj * N + bn;
    const int NT = K >> 4;

    // issue one k-tile's copies into stage s
    #define ISSUE(t, s) do {                                                   \
        cp16(&As[s][arow][ahalf * 4], Asrc + (t) * 16);                        \
        const unsigned* _b = Bsrc + (long)(t) * 8 * N;                        \
        cp8(&Bs[s][bj][2 * (bl      )], _b + 2 * (bl      ));                  \
        cp8(&Bs[s][bj][2 * (bl + 32 )], _b + 2 * (bl + 32 ));                  \
        cp8(&Bs[s][bj][2 * (bl + 64 )], _b + 2 * (bl + 64 ));                  \
        cp8(&Bs[s][bj][2 * (bl + 96 )], _b + 2 * (bl + 96 ));                  \
        asm volatile("cp.async.commit_group;\n");                              \
    } while (0)

    ISSUE(0, 0);
    ISSUE(1, 1);
    asm volatile("cp.async.wait_group 1;\n");
    __syncthreads();

    int stage = 0;
    for (int t = 0; t < NT; t++) {
        // compute current stage
        unsigned af[4][4];
        #pragma unroll
        for (int mt = 0; mt < 4; mt++) {
            int r0 = warpM + mt * 16 + gid;
            af[mt][0] = As[stage][r0    ][tig];
            af[mt][1] = As[stage][r0 + 8][tig];
            af[mt][2] = As[stage][r0    ][tig + 4];
            af[mt][3] = As[stage][r0 + 8][tig + 4];
        }
        #pragma unroll
        for (int nt = 0; nt < 8; nt++) {
            int cc = warpN + nt * 8 + gid;
            unsigned b0 = Bs[stage][tig    ][cc];
            unsigned b1 = Bs[stage][tig + 4][cc];
            #pragma unroll
            for (int mt = 0; mt < 4; mt++)
                mma_bf16(acc[mt][nt], af[mt], b0, b1);
        }
        // prefetch t+2, then ensure t+1 is resident
        int s2 = stage + 2; if (s2 >= 3) s2 -= 3;
        if (t + 2 < NT) {
            ISSUE(t + 2, s2);
            asm volatile("cp.async.wait_group 1;\n");
        } else {
            asm volatile("cp.async.wait_group 0;\n");
        }
        __syncthreads();
        stage = (stage + 1 < 3) ? stage + 1 : 0;
    }
    #undef ISSUE

    // epilogue
    #pragma unroll
    for (int mt = 0; mt < 4; mt++) {
        long r0 = bm + warpM + mt * 16 + gid;
        #pragma unroll
        for (int nt = 0; nt < 8; nt++) {
            long c0 = bn + warpN + nt * 8 + tig * 2;
            float bv0 = bias[c0], bv1 = bias[c0 + 1];
            float v00 = acc[mt][nt][0] + bv0;
            float v01 = acc[mt][nt][1] + bv1;
            float v10 = acc[mt][nt][2] + bv0;
            float v11 = acc[mt][nt][3] + bv1;
            if (EPI == 1) {
                v00 = 0.5f * v00 * (1.f + erff(v00 * 0.70710678118654752f));
                v01 = 0.5f * v01 * (1.f + erff(v01 * 0.70710678118654752f));
                v10 = 0.5f * v10 * (1.f + erff(v10 * 0.70710678118654752f));
                v11 = 0.5f * v11 * (1.f + erff(v11 * 0.70710678118654752f));
            } else if (EPI == 2) {
                v00 += R[r0 * N + c0];
                v01 += R[r0 * N + c0 + 1];
                v10 += R[(r0 + 8) * N + c0];
                v11 += R[(r0 + 8) * N + c0 + 1];
            }
            if (EPI == 2) {
                float* C = (float*)Cout;
                *(float2*)&C[r0 * N + c0]       = make_float2(v00, v01);
                *(float2*)&C[(r0 + 8) * N + c0] = make_float2(v10, v11);
            } else {
                __nv_bfloat16* C = (__nv_bfloat16*)Cout;
                *(unsigned*)&C[r0 * N + c0]       = pkbf(v00, v01);
                *(unsigned*)&C[(r0 + 8) * N + c0] = pkbf(v10, v11);
            }
        }
    }
}

// ---------------- Flash attention, bf16 TCs, BQ=128, 256 threads --------------
// 8 warps; warp w owns q-rows [w*16, w*16+16). KV tile 64. Same per-row math
// and kv order as before -> bit-identical output.
__global__ __launch_bounds__(256)
void attn_tc(const __nv_bfloat16* __restrict__ QKV, __nv_bfloat16* __restrict__ O)
{
    extern __shared__ unsigned smem[];
    unsigned* Qs = smem;               // [128 qrow][32 dpair pad 36]
    unsigned* Ks = Qs + 128 * 36;      // [64 kvrow][32 dpair pad 36]
    unsigned* Vs = Ks + 64 * 36;       // [32 kvpair][64 d pad 72]
    unsigned* Ps = Vs + 32 * 72;       // [128 qrow][32 kvpair pad 36]

    const int tid  = threadIdx.x;
    const int wid  = tid >> 5;
    const int lane = tid & 31;
    const int gid  = lane >> 2;
    const int tig  = lane & 3;
    const int w16  = wid * 16;
    const int q0   = blockIdx.x * 128;
    const int b    = blockIdx.y / HH;
    const int h    = blockIdx.y % HH;
    const long hq  = (long)h * HD;
    const long hk  = hq + DD;
    const long hv  = hq + 2 * DD;
    const long rowbase = (long)b * SS;

    // Q tile: 128 rows x 8 uint4-chunks
    #pragma unroll
    for (int l = 0; l < 4; l++) {
        int f   = tid + l * 256;       // 0..1023
        int row = f >> 3;
        int c   = f & 7;
        uint4 v = *(const uint4*)&QKV[(rowbase + q0 + row) * QS + hq + c * 8];
        *(uint4*)&Qs[row * 36 + c * 4] = v;
    }

    float m0 = -INFINITY, m1 = -INFINITY, l0 = 0.f, l1 = 0.f;
    float o[8][4];
    #pragma unroll
    for (int nt = 0; nt < 8; nt++)
        #pragma unroll
        for (int r = 0; r < 4; r++) o[nt][r] = 0.f;

    for (int t = 0; t < SS / 64; t++) {
        __syncthreads();
        const int k0 = t * 64;
        #pragma unroll
        for (int l = 0; l < 2; l++) {
            int f   = tid + l * 256;   // 0..511
            int row = f >> 3;
            int c   = f & 7;
            uint4 v = *(const uint4*)&QKV[(rowbase + k0 + row) * QS + hk + c * 8];
            *(uint4*)&Ks[row * 36 + c * 4] = v;
        }
        {
            int f = tid;               // 0..255
            int j = f >> 3;
            int c = f & 7;
            uint4 lo = *(const uint4*)&QKV[(rowbase + k0 + 2*j    ) * QS + hv + c * 8];
            uint4 hi = *(const uint4*)&QKV[(rowbase + k0 + 2*j + 1) * QS + hv + c * 8];
            uint4 o0, o1;
            o0.x = __byte_perm(lo.x, hi.x, 0x5410); o0.y = __byte_perm(lo.x, hi.x, 0x7632);
            o0.z = __byte_perm(lo.y, hi.y, 0x5410); o0.w = __byte_perm(lo.y, hi.y, 0x7632);
            o1.x = __byte_perm(lo.z, hi.z, 0x5410); o1.y = __byte_perm(lo.z, hi.z, 0x7632);
            o1.z = __byte_perm(lo.w, hi.w, 0x5410); o1.w = __byte_perm(lo.w, hi.w, 0x7632);
            *(uint4*)&Vs[j * 72 + c * 8]     = o0;
            *(uint4*)&Vs[j * 72 + c * 8 + 4] = o1;
        }
        __syncthreads();

        // S = Q @ K^T
        float sacc[8][4];
        #pragma unroll
        for (int nt = 0; nt < 8; nt++)
            #pragma unroll
            for (int r = 0; r < 4; r++) sacc[nt][r] = 0.f;
        #pragma unroll
        for (int kt = 0; kt < 4; kt++) {
            unsigned a[4];
            a[0] = Qs[(w16 + gid    ) * 36 + kt * 8 + tig];
            a[1] = Qs[(w16 + gid + 8) * 36 + kt * 8 + tig];
            a[2] = Qs[(w16 + gid    ) * 36 + kt * 8 + tig + 4];
            a[3] = Qs[(w16 + gid + 8) * 36 + kt * 8 + tig + 4];
            #pragma unroll
            for (int nt = 0; nt < 8; nt++) {
                unsigned b0 = Ks[(nt * 8 + gid) * 36 + kt * 8 + tig];
                unsigned b1 = Ks[(nt * 8 + gid) * 36 + kt * 8 + tig + 4];
                mma_bf16(sacc[nt], a, b0, b1);
            }
        }

        // online softmax
        float p[8][4];
        float rm0 = -INFINITY, rm1 = -INFINITY;
        #pragma unroll
        for (int nt = 0; nt < 8; nt++) {
            #pragma unroll
            for (int r = 0; r < 4; r++) p[nt][r] = sacc[nt][r] * 0.125f;
            rm0 = fmaxf(rm0, fmaxf(p[nt][0], p[nt][1]));
            rm1 = fmaxf(rm1, fmaxf(p[nt][2], p[nt][3]));
        }
        #pragma unroll
        for (int off = 1; off < 4; off <<= 1) {
            rm0 = fmaxf(rm0, __shfl_xor_sync(0xffffffffu, rm0, off));
            rm1 = fmaxf(rm1, __shfl_xor_sync(0xffffffffu, rm1, off));
        }
        float mn0 = fmaxf(m0, rm0), mn1 = fmaxf(m1, rm1);
        float corr0 = __expf(m0 - mn0), corr1 = __expf(m1 - mn1);
        m0 = mn0; m1 = mn1;
        float rs0 = 0.f, rs1 = 0.f;
        #pragma unroll
        for (int nt = 0; nt < 8; nt++) {
            p[nt][0] = __expf(p[nt][0] - mn0);
            p[nt][1] = __expf(p[nt][1] - mn0);
            p[nt][2] = __expf(p[nt][2] - mn1);
            p[nt][3] = __expf(p[nt][3] - mn1);
            rs0 += p[nt][0] + p[nt][1];
            rs1 += p[nt][2] + p[nt][3];
        }
        #pragma unroll
        for (int off = 1; off < 4; off <<= 1) {
            rs0 += __shfl_xor_sync(0xffffffffu, rs0, off);
            rs1 += __shfl_xor_sync(0xffffffffu, rs1, off);
        }
        l0 = l0 * corr0 + rs0;
        l1 = l1 * corr1 + rs1;
        #pragma unroll
        for (int nt = 0; nt < 8; nt++) {
            o[nt][0] *= corr0; o[nt][1] *= corr0;
            o[nt][2] *= corr1; o[nt][3] *= corr1;
        }

        // P -> smem (own rows only)
        #pragma unroll
        for (int nt = 0; nt < 8; nt++) {
            Ps[(w16 + gid    ) * 36 + nt * 4 + tig] = pkbf(p[nt][0], p[nt][1]);
            Ps[(w16 + gid + 8) * 36 + nt * 4 + tig] = pkbf(p[nt][2], p[nt][3]);
        }
        __syncwarp();

        // O += P @ V
        #pragma unroll
        for (int kt = 0; kt < 4; kt++) {
            unsigned a[4];
            a[0] = Ps[(w16 + gid    ) * 36 + kt * 8 + tig];
            a[1] = Ps[(w16 + gid + 8) * 36 + kt * 8 + tig];
            a[2] = Ps[(w16 + gid    ) * 36 + kt * 8 + tig + 4];
            a[3] = Ps[(w16 + gid + 8) * 36 + kt * 8 + tig + 4];
            #pragma unroll
            for (int nt = 0; nt < 8; nt++) {
                unsigned b0 = Vs[(kt * 8 + tig    ) * 72 + nt * 8 + gid];
                unsigned b1 = Vs[(kt * 8 + tig + 4) * 72 + nt * 8 + gid];
                mma_bf16(o[nt], a, b0, b1);
            }
        }
        __syncwarp();
    }

    const float inv0 = 1.f / l0, inv1 = 1.f / l1;
    const long r0 = rowbase + q0 + w16 + gid;
    #pragma unroll
    for (int nt = 0; nt < 8; nt++) {
        long c = (long)h * HD + nt * 8 + tig * 2;
        *(unsigned*)&O[r0 * DD + c]       = pkbf(o[nt][0] * inv0, o[nt][1] * inv0);
        *(unsigned*)&O[(r0 + 8) * DD + c] = pkbf(o[nt][2] * inv1, o[nt][3] * inv1);
    }
}

// ---------------- launch -----------------------------------------------------
extern "C" void kernel_launch(void* const* d_in, const int* in_sizes, int n_in,
                              void* d_out, int out_size)
{
    const float* x   = (const float*)d_in[0];
    const float* Wq  = (const float*)d_in[1];
    const float* bq  = (const float*)d_in[2];
    const float* Wk  = (const float*)d_in[3];
    const float* bk  = (const float*)d_in[4];
    const float* Wv  = (const float*)d_in[5];
    const float* bv  = (const float*)d_in[6];
    const float* Wo  = (const float*)d_in[7];
    const float* bo  = (const float*)d_in[8];
    const float* W1  = (const float*)d_in[9];
    const float* b1  = (const float*)d_in[10];
    const float* W2  = (const float*)d_in[11];
    const float* b2  = (const float*)d_in[12];
    const float* g1  = (const float*)d_in[13];
    const float* be1 = (const float*)d_in[14];
    const float* g2  = (const float*)d_in[15];
    const float* be2 = (const float*)d_in[16];
    float* out = (float*)d_out;

    __nv_bfloat16 *p_xnb, *p_qkvb, *p_attb, *p_hb;
    float *p_x1, *p_bqkv;
    unsigned *p_wqkvp, *p_wop, *p_w1p, *p_w2p;
    cudaGetSymbolAddress((void**)&p_xnb,   g_xnb);
    cudaGetSymbolAddress((void**)&p_qkvb,  g_qkvb);
    cudaGetSymbolAddress((void**)&p_attb,  g_attb);
    cudaGetSymbolAddress((void**)&p_hb,    g_hb);
    cudaGetSymbolAddress((void**)&p_x1,    g_x1);
    cudaGetSymbolAddress((void**)&p_wqkvp, g_wqkvp);
    cudaGetSymbolAddress((void**)&p_wop,   g_wop);
    cudaGetSymbolAddress((void**)&p_w1p,   g_w1p);
    cudaGetSymbolAddress((void**)&p_w2p,   g_w2p);
    cudaGetSymbolAddress((void**)&p_bqkv,  g_bqkv);

    const int attn_smem = (128*36 + 64*36 + 32*72 + 128*36) * (int)sizeof(unsigned); // 55296 B
    cudaFuncSetAttribute(attn_tc, cudaFuncAttributeMaxDynamicSharedMemorySize, attn_smem);

    // 0. pack weights to bf16 (k-paired layout)
    pack_qkv<<<((DD/2)*3*DD + 255)/256, 256>>>(Wq, Wk, Wv, bq, bk, bv, p_wqkvp, p_bqkv);
    pack_w<<<((DD/2)*DD + 255)/256, 256>>>(Wo, p_wop, DD, DD);
    pack_w<<<((DD/2)*FF + 255)/256, 256>>>(W1, p_w1p, DD, FF);
    pack_w<<<((FF/2)*DD + 255)/256, 256>>>(W2, p_w2p, FF, DD);

    // 1. LN1 -> bf16
    ln_kernel<<<ROWS, 256>>>(x, g1, be1, p_xnb);
    // 2. fused QKV projection (one GEMM, N=3072)
    dim3 qkvGrid(3*DD/256, ROWS/128);        // (12, 64)
    gemm_bf16<0><<<qkvGrid, 256>>>(p_xnb, p_wqkvp, p_bqkv, nullptr, p_qkvb, ROWS, 3*DD, DD);
    // 3. attention (BQ=128, 256 threads)
    dim3 attnGrid(SS/128, BB*HH);            // (16, 64)
    attn_tc<<<attnGrid, 256, attn_smem>>>(p_qkvb, p_attb);
    // 4. output projection + residual (fp32 out)
    dim3 gridDD(DD/256, ROWS/128);           // (4, 64)
    gemm_bf16<2><<<gridDD, 256>>>(p_attb, p_wop, bo, x, p_x1, ROWS, DD, DD);
    // 5. LN2 -> bf16
    ln_kernel<<<ROWS, 256>>>(p_x1, g2, be2, p_xnb);
    // 6. FFN up + GELU -> bf16
    dim3 gridDF(FF/256, ROWS/128);           // (16, 64)
    gemm_bf16<1><<<gridDF, 256>>>(p_xnb, p_w1p, b1, nullptr, p_hb, ROWS, FF, DD);
    // 7. FFN down + residual -> out (fp32)
    gemm_bf16<2><<<gridDD, 256>>>(p_hb, p_w2p, b2, p_x1, out, ROWS, DD, FF);
}